// round 1
// baseline (speedup 1.0000x reference)
#include <cuda_runtime.h>

// Problem dims (fixed by the dataset)
#define B_   32
#define CIN  32
#define T_   12
#define N_   1024
#define KS   3
#define COUT 64
#define R_   (B_ * CIN * T_)   // 12288 rows for stage-1 GEMM

// Stage-1 scratch: x_c[k][r][n], k-major slabs. 3 * 12288 * 1024 floats = 151 MB.
__device__ float g_xc[(size_t)KS * R_ * N_];

// ---------------------------------------------------------------------------
// Stage 1:  x_c[k][r][n] = sum_m x[r][m] * Lk[k][n][m]
// Classic 128x128x8 fp32 SGEMM (NT), 256 threads, 8x8 per thread, float4 I/O.
// ---------------------------------------------------------------------------
__global__ __launch_bounds__(256) void stage1_gemm(
    const float* __restrict__ X,   // [R_][N_]  (r = (b*CIN+i)*T_+t, m contiguous)
    const float* __restrict__ Lk)  // [KS][N_][N_] (n rows, m contiguous)
{
    const int k     = blockIdx.z;
    const int rBase = blockIdx.y * 128;
    const int nBase = blockIdx.x * 128;

    const float* A = X;                                   // row r, col m
    const float* Bm = Lk + (size_t)k * N_ * N_;           // row n, col m
    float*       C  = g_xc + (size_t)k * R_ * N_;

    __shared__ float As[8][128];
    __shared__ float Bs[8][128];

    const int tid = threadIdx.x;
    const int tx  = tid % 16;     // col group
    const int ty  = tid / 16;     // row group

    // loader mapping: 128 rows x 8 cols = 1024 floats = 256 threads x float4
    const int lrow  = tid >> 1;        // 0..127
    const int lcol4 = (tid & 1) * 4;   // 0 or 4

    const float* Aptr = A  + (size_t)(rBase + lrow) * N_ + lcol4;
    const float* Bptr = Bm + (size_t)(nBase + lrow) * N_ + lcol4;

    float acc[8][8];
    #pragma unroll
    for (int i = 0; i < 8; i++)
        #pragma unroll
        for (int j = 0; j < 8; j++) acc[i][j] = 0.0f;

    // preload tile 0
    float4 a4 = *(const float4*)Aptr;
    float4 b4 = *(const float4*)Bptr;

    for (int kt = 0; kt < N_; kt += 8) {
        // store (transposed) to smem
        As[lcol4 + 0][lrow] = a4.x;
        As[lcol4 + 1][lrow] = a4.y;
        As[lcol4 + 2][lrow] = a4.z;
        As[lcol4 + 3][lrow] = a4.w;
        Bs[lcol4 + 0][lrow] = b4.x;
        Bs[lcol4 + 1][lrow] = b4.y;
        Bs[lcol4 + 2][lrow] = b4.z;
        Bs[lcol4 + 3][lrow] = b4.w;
        __syncthreads();

        // prefetch next K-tile while computing on this one
        if (kt + 8 < N_) {
            a4 = *(const float4*)(Aptr + kt + 8);
            b4 = *(const float4*)(Bptr + kt + 8);
        }

        #pragma unroll
        for (int kk = 0; kk < 8; kk++) {
            float4 a0 = *(const float4*)&As[kk][ty * 4];
            float4 a1 = *(const float4*)&As[kk][ty * 4 + 64];
            float4 b0 = *(const float4*)&Bs[kk][tx * 4];
            float4 b1 = *(const float4*)&Bs[kk][tx * 4 + 64];
            float ar[8] = {a0.x, a0.y, a0.z, a0.w, a1.x, a1.y, a1.z, a1.w};
            float br[8] = {b0.x, b0.y, b0.z, b0.w, b1.x, b1.y, b1.z, b1.w};
            #pragma unroll
            for (int ii = 0; ii < 8; ii++)
                #pragma unroll
                for (int jj = 0; jj < 8; jj++)
                    acc[ii][jj] = fmaf(ar[ii], br[jj], acc[ii][jj]);
        }
        __syncthreads();
    }

    // write back: rows {ty*4+0..3, 64+ty*4+0..3}, cols {tx*4+0..3, 64+tx*4+0..3}
    #pragma unroll
    for (int ii = 0; ii < 8; ii++) {
        int row = rBase + ((ii < 4) ? (ty * 4 + ii) : (64 + ty * 4 + (ii - 4)));
        float4 v0 = make_float4(acc[ii][0], acc[ii][1], acc[ii][2], acc[ii][3]);
        float4 v1 = make_float4(acc[ii][4], acc[ii][5], acc[ii][6], acc[ii][7]);
        *(float4*)&C[(size_t)row * N_ + nBase + tx * 4]      = v0;
        *(float4*)&C[(size_t)row * N_ + nBase + 64 + tx * 4] = v1;
    }
}

// ---------------------------------------------------------------------------
// Stage 2:  out[b,o,t,n] = relu( sum_{k,i} theta[i,o,k]*x_c[k][(b*32+i)*12+t][n]
//                                + bias[o] + (o<32 ? x[b,o,t,n] : 0) )
// Block = one (b, t, 128-wide n slice). K = 96 (=ks*c_in), chunked by k.
// ---------------------------------------------------------------------------
__global__ __launch_bounds__(256) void stage2_fused(
    const float* __restrict__ X,      // [B_][CIN][T_][N_]
    const float* __restrict__ theta,  // [CIN][COUT][KS]
    const float* __restrict__ bias,   // [COUT]
    float* __restrict__ out)          // [B_][COUT][T_][N_]
{
    const int n0 = blockIdx.x * 128;
    const int t  = blockIdx.y;
    const int bb = blockIdx.z;

    __shared__ float th_s[96][64];    // [ik = k*32+i][o]   24 KB
    __shared__ float xs[32][128];     // one k-chunk        16 KB
    __shared__ float bias_s[64];

    const int tid = threadIdx.x;
    const int tx  = tid % 32;   // n group: n = n0 + tx*4 .. +3
    const int ty  = tid / 32;   // o group: o = ty*8 .. +7

    // load theta reorganized as [ik][o]
    for (int idx = tid; idx < 96 * 64; idx += 256) {
        int ik = idx / 64, o = idx % 64;
        int k = ik / 32, i = ik % 32;
        th_s[ik][o] = theta[i * (COUT * KS) + o * KS + k];
    }
    if (tid < 64) bias_s[tid] = bias[tid];

    float acc[4][8];
    #pragma unroll
    for (int nn = 0; nn < 4; nn++)
        #pragma unroll
        for (int oo = 0; oo < 8; oo++) acc[nn][oo] = 0.0f;

    for (int c = 0; c < KS; c++) {   // chunk c == k (chunks align with k slabs)
        __syncthreads();             // also orders th_s/bias before first use
        // load xs[rr=i][n0..n0+127] for k=c
        const float* src = g_xc + (size_t)c * R_ * N_;
        #pragma unroll
        for (int rep = 0; rep < 4; rep++) {
            int idx = rep * 256 + tid;      // 0..1023
            int rr  = idx / 32;             // i
            int c4  = idx % 32;             // float4 column
            float4 v = *(const float4*)&src[((size_t)(bb * CIN + rr) * T_ + t) * N_ + n0 + c4 * 4];
            *(float4*)&xs[rr][c4 * 4] = v;
        }
        __syncthreads();

        #pragma unroll
        for (int kk = 0; kk < 32; kk++) {
            int ik = c * 32 + kk;
            float4 xv = *(const float4*)&xs[kk][tx * 4];
            float4 t0 = *(const float4*)&th_s[ik][ty * 8];
            float4 t1 = *(const float4*)&th_s[ik][ty * 8 + 4];
            float xr[4] = {xv.x, xv.y, xv.z, xv.w};
            float tr[8] = {t0.x, t0.y, t0.z, t0.w, t1.x, t1.y, t1.z, t1.w};
            #pragma unroll
            for (int nn = 0; nn < 4; nn++)
                #pragma unroll
                for (int oo = 0; oo < 8; oo++)
                    acc[nn][oo] = fmaf(xr[nn], tr[oo], acc[nn][oo]);
        }
    }

    // epilogue: bias + pad-residual + relu, vectorized stores
    const int o0 = ty * 8;
    #pragma unroll
    for (int oo = 0; oo < 8; oo++) {
        int o = o0 + oo;
        float v0 = acc[0][oo] + bias_s[o];
        float v1 = acc[1][oo] + bias_s[o];
        float v2 = acc[2][oo] + bias_s[o];
        float v3 = acc[3][oo] + bias_s[o];
        if (o < CIN) {
            float4 r = *(const float4*)&X[((size_t)(bb * CIN + o) * T_ + t) * N_ + n0 + tx * 4];
            v0 += r.x; v1 += r.y; v2 += r.z; v3 += r.w;
        }
        float4 w = make_float4(fmaxf(v0, 0.f), fmaxf(v1, 0.f),
                               fmaxf(v2, 0.f), fmaxf(v3, 0.f));
        *(float4*)&out[((size_t)(bb * COUT + o) * T_ + t) * N_ + n0 + tx * 4] = w;
    }
}

extern "C" void kernel_launch(void* const* d_in, const int* in_sizes, int n_in,
                              void* d_out, int out_size)
{
    const float* x     = (const float*)d_in[0];  // (32,32,12,1024)
    const float* Lk    = (const float*)d_in[1];  // (3,1024,1024)
    const float* theta = (const float*)d_in[2];  // (32,64,3)
    const float* bias  = (const float*)d_in[3];  // (1,64,1,1)
    float* out = (float*)d_out;                  // (32,64,12,1024)

    dim3 g1(N_ / 128, R_ / 128, KS);   // (8, 96, 3)
    stage1_gemm<<<g1, 256>>>(x, Lk);

    dim3 g2(N_ / 128, T_, B_);         // (8, 12, 32)
    stage2_fused<<<g2, 256>>>(x, theta, bias, out);
}

// round 3
// speedup vs baseline: 1.9661x; 1.9661x over previous
#include <cuda_runtime.h>
#include <cuda_bf16.h>
#include <cstdint>

// Problem dims (fixed by the dataset)
#define B_   32
#define CIN  32
#define T_   12
#define N_   1024
#define KS   3
#define COUT 64
#define R_   (B_ * CIN * T_)   // 12288

// Scratch (__device__ globals; no allocations allowed)
__device__ float         g_xc [(size_t)KS * R_ * N_];    // 151 MB fp32
__device__ __nv_bfloat16 g_xhi[(size_t)R_ * N_];
__device__ __nv_bfloat16 g_xlo[(size_t)R_ * N_];
__device__ __nv_bfloat16 g_lhi[(size_t)KS * N_ * N_];
__device__ __nv_bfloat16 g_llo[(size_t)KS * N_ * N_];

__device__ __forceinline__ uint32_t smem_u32(const void* p) {
    uint32_t a;
    asm("{ .reg .u64 t; cvta.to.shared.u64 t, %1; cvt.u32.u64 %0, t; }"
        : "=r"(a) : "l"(p));
    return a;
}
__device__ __forceinline__ void cp16(uint32_t dst, const void* src) {
    asm volatile("cp.async.cg.shared.global [%0], [%1], 16;" :: "r"(dst), "l"(src));
}
#define CP_COMMIT() asm volatile("cp.async.commit_group;" ::: "memory")
#define CP_WAIT(n)  asm volatile("cp.async.wait_group %0;" :: "n"(n) : "memory")

// D += A*B, m16n8k16, bf16 in / fp32 acc
#define MMA_BF16(d, a, b)                                                     \
    asm volatile("mma.sync.aligned.m16n8k16.row.col.f32.bf16.bf16.f32 "       \
                 "{%0,%1,%2,%3}, {%4,%5,%6,%7}, {%8,%9}, {%0,%1,%2,%3};"      \
                 : "+f"((d)[0]), "+f"((d)[1]), "+f"((d)[2]), "+f"((d)[3])     \
                 : "r"((a)[0]), "r"((a)[1]), "r"((a)[2]), "r"((a)[3]),        \
                   "r"((b)[0]), "r"((b)[1]))

// ---------------------------------------------------------------------------
// fp32 -> bf16 hi + lo residual splits
// ---------------------------------------------------------------------------
__global__ __launch_bounds__(256) void split_x(const float* __restrict__ src) {
    size_t i = ((size_t)blockIdx.x * 256 + threadIdx.x) * 4;
    float4 v = *(const float4*)(src + i);
    float f[4] = {v.x, v.y, v.z, v.w};
    __nv_bfloat16 h[4], l[4];
    #pragma unroll
    for (int j = 0; j < 4; j++) {
        h[j] = __float2bfloat16(f[j]);
        l[j] = __float2bfloat16(f[j] - __bfloat162float(h[j]));
    }
    *(__nv_bfloat162*)(g_xhi + i)     = __halves2bfloat162(h[0], h[1]);
    *(__nv_bfloat162*)(g_xhi + i + 2) = __halves2bfloat162(h[2], h[3]);
    *(__nv_bfloat162*)(g_xlo + i)     = __halves2bfloat162(l[0], l[1]);
    *(__nv_bfloat162*)(g_xlo + i + 2) = __halves2bfloat162(l[2], l[3]);
}
__global__ __launch_bounds__(256) void split_l(const float* __restrict__ src) {
    size_t i = ((size_t)blockIdx.x * 256 + threadIdx.x) * 4;
    float4 v = *(const float4*)(src + i);
    float f[4] = {v.x, v.y, v.z, v.w};
    __nv_bfloat16 h[4], l[4];
    #pragma unroll
    for (int j = 0; j < 4; j++) {
        h[j] = __float2bfloat16(f[j]);
        l[j] = __float2bfloat16(f[j] - __bfloat162float(h[j]));
    }
    *(__nv_bfloat162*)(g_lhi + i)     = __halves2bfloat162(h[0], h[1]);
    *(__nv_bfloat162*)(g_lhi + i + 2) = __halves2bfloat162(h[2], h[3]);
    *(__nv_bfloat162*)(g_llo + i)     = __halves2bfloat162(l[0], l[1]);
    *(__nv_bfloat162*)(g_llo + i + 2) = __halves2bfloat162(l[2], l[3]);
}

// ---------------------------------------------------------------------------
// Stage 1: x_c[k][r][n] = sum_m X[r][m]*Lk[k][n][m]  via mma.sync bf16 x3
// CTA tile 128(M) x 256(N), kc=32, 256 threads (8 warps of 64x64).
// Smem rows padded to 80B -> conflict-free fragment LDS.
// ---------------------------------------------------------------------------
#define KC        32
#define STG_A_H   0
#define STG_A_L   10240
#define STG_B_H   20480
#define STG_B_L   40960
#define STG_STRIDE 61440
#define S1_SMEM   (2 * STG_STRIDE)   // 120 KB

__global__ __launch_bounds__(256, 1) void stage1_mma() {
    extern __shared__ char smem[];
    const uint32_t sb = smem_u32(smem);

    const int tid  = threadIdx.x;
    const int lane = tid & 31;
    const int wid  = tid >> 5;
    const int wr   = wid >> 2;    // warp row 0..1 (64 rows each)
    const int wc   = wid & 3;     // warp col 0..3 (64 cols each)
    const int gid  = lane >> 2;   // 0..7
    const int tig  = lane & 3;    // 0..3

    const int kz    = blockIdx.z;
    const int rBase = blockIdx.y * 128;
    const int nBase = blockIdx.x * 256;

    const __nv_bfloat16* Ah = g_xhi + (size_t)rBase * N_;
    const __nv_bfloat16* Al = g_xlo + (size_t)rBase * N_;
    const __nv_bfloat16* Bh = g_lhi + ((size_t)kz * N_ + nBase) * N_;
    const __nv_bfloat16* Bl = g_llo + ((size_t)kz * N_ + nBase) * N_;

    // async copy of one k-chunk into stage (c&1)
    auto issue = [&](int c) {
        const uint32_t stg = sb + (uint32_t)(c & 1) * STG_STRIDE;
        const int kofs = c * KC;
        #pragma unroll
        for (int j = 0; j < 12; j++) {
            const int idx = j * 256 + tid;
            if (j < 2) {                     // A hi: 512 chunks
                int q = idx, row = q >> 2, c16 = q & 3;
                cp16(stg + STG_A_H + row * 80 + c16 * 16,
                     Ah + (size_t)row * N_ + kofs + c16 * 8);
            } else if (j < 4) {              // A lo
                int q = idx - 512, row = q >> 2, c16 = q & 3;
                cp16(stg + STG_A_L + row * 80 + c16 * 16,
                     Al + (size_t)row * N_ + kofs + c16 * 8);
            } else if (j < 8) {              // B hi: 1024 chunks
                int q = idx - 1024, row = q >> 2, c16 = q & 3;
                cp16(stg + STG_B_H + row * 80 + c16 * 16,
                     Bh + (size_t)row * N_ + kofs + c16 * 8);
            } else {                         // B lo
                int q = idx - 2048, row = q >> 2, c16 = q & 3;
                cp16(stg + STG_B_L + row * 80 + c16 * 16,
                     Bl + (size_t)row * N_ + kofs + c16 * 8);
            }
        }
        CP_COMMIT();
    };

    float acc[4][8][4];
    #pragma unroll
    for (int mt = 0; mt < 4; mt++)
        #pragma unroll
        for (int nt = 0; nt < 8; nt++)
            #pragma unroll
            for (int q = 0; q < 4; q++) acc[mt][nt][q] = 0.0f;

    issue(0);
    issue(1);

    const int NCHUNK = N_ / KC;   // 32
    for (int c = 0; c < NCHUNK; c++) {
        if (c < NCHUNK - 1) CP_WAIT(1); else CP_WAIT(0);
        __syncthreads();

        const char* base = smem + (size_t)(c & 1) * STG_STRIDE;
        const char* sAh = base + STG_A_H;
        const char* sAl = base + STG_A_L;
        const char* sBh = base + STG_B_H;
        const char* sBl = base + STG_B_L;

        #pragma unroll
        for (int kst = 0; kst < 2; kst++) {
            const int kb = kst * 32;   // byte offset of 16-k step

            uint32_t ah[4][4], al[4][4];
            #pragma unroll
            for (int mt = 0; mt < 4; mt++) {
                const uint32_t off = (uint32_t)(wr * 64 + mt * 16 + gid) * 80
                                   + tig * 4 + kb;
                ah[mt][0] = *(const uint32_t*)(sAh + off);
                ah[mt][1] = *(const uint32_t*)(sAh + off + 640);
                ah[mt][2] = *(const uint32_t*)(sAh + off + 16);
                ah[mt][3] = *(const uint32_t*)(sAh + off + 656);
                al[mt][0] = *(const uint32_t*)(sAl + off);
                al[mt][1] = *(const uint32_t*)(sAl + off + 640);
                al[mt][2] = *(const uint32_t*)(sAl + off + 16);
                al[mt][3] = *(const uint32_t*)(sAl + off + 656);
            }

            #pragma unroll
            for (int ntb = 0; ntb < 2; ntb++) {
                uint32_t bh[4][2], bl[4][2];
                #pragma unroll
                for (int q = 0; q < 4; q++) {
                    const int nt = ntb * 4 + q;
                    const uint32_t off = (uint32_t)(wc * 64 + nt * 8 + gid) * 80
                                       + tig * 4 + kb;
                    bh[q][0] = *(const uint32_t*)(sBh + off);
                    bh[q][1] = *(const uint32_t*)(sBh + off + 16);
                    bl[q][0] = *(const uint32_t*)(sBl + off);
                    bl[q][1] = *(const uint32_t*)(sBl + off + 16);
                }
                #pragma unroll
                for (int mt = 0; mt < 4; mt++)
                    #pragma unroll
                    for (int q = 0; q < 4; q++) {
                        float* d = acc[mt][ntb * 4 + q];
                        MMA_BF16(d, ah[mt], bh[q]);   // hi*hi
                        MMA_BF16(d, ah[mt], bl[q]);   // hi*lo
                        MMA_BF16(d, al[mt], bh[q]);   // lo*hi
                    }
            }
        }
        __syncthreads();
        if (c + 2 < NCHUNK) issue(c + 2);
    }

    // epilogue: fp32 acc -> g_xc
    float* C = g_xc + (size_t)kz * R_ * N_;
    const int rw = rBase + wr * 64;
    const int cw = nBase + wc * 64;
    #pragma unroll
    for (int mt = 0; mt < 4; mt++) {
        #pragma unroll
        for (int nt = 0; nt < 8; nt++) {
            const int r0 = rw + mt * 16 + gid;
            const int c0 = cw + nt * 8 + tig * 2;
            float2 v01 = make_float2(acc[mt][nt][0], acc[mt][nt][1]);
            float2 v23 = make_float2(acc[mt][nt][2], acc[mt][nt][3]);
            *(float2*)&C[(size_t)r0 * N_ + c0]       = v01;
            *(float2*)&C[(size_t)(r0 + 8) * N_ + c0] = v23;
        }
    }
}

// ---------------------------------------------------------------------------
// Stage 2 (unchanged): out = relu(theta-contraction + bias + pad-residual)
// ---------------------------------------------------------------------------
__global__ __launch_bounds__(256) void stage2_fused(
    const float* __restrict__ X,
    const float* __restrict__ theta,
    const float* __restrict__ bias,
    float* __restrict__ out)
{
    const int n0 = blockIdx.x * 128;
    const int t  = blockIdx.y;
    const int bb = blockIdx.z;

    __shared__ float th_s[96][64];
    __shared__ float xs[32][128];
    __shared__ float bias_s[64];

    const int tid = threadIdx.x;
    const int tx  = tid % 32;
    const int ty  = tid / 32;

    for (int idx = tid; idx < 96 * 64; idx += 256) {
        int ik = idx / 64, o = idx % 64;
        int k = ik / 32, i = ik % 32;
        th_s[ik][o] = theta[i * (COUT * KS) + o * KS + k];
    }
    if (tid < 64) bias_s[tid] = bias[tid];

    float acc[4][8];
    #pragma unroll
    for (int nn = 0; nn < 4; nn++)
        #pragma unroll
        for (int oo = 0; oo < 8; oo++) acc[nn][oo] = 0.0f;

    for (int c = 0; c < KS; c++) {
        __syncthreads();
        const float* src = g_xc + (size_t)c * R_ * N_;
        #pragma unroll
        for (int rep = 0; rep < 4; rep++) {
            int idx = rep * 256 + tid;
            int rr  = idx / 32;
            int c4  = idx % 32;
            float4 v = *(const float4*)&src[((size_t)(bb * CIN + rr) * T_ + t) * N_ + n0 + c4 * 4];
            *(float4*)&xs[rr][c4 * 4] = v;
        }
        __syncthreads();

        #pragma unroll
        for (int kk = 0; kk < 32; kk++) {
            int ik = c * 32 + kk;
            float4 xv = *(const float4*)&xs[kk][tx * 4];
            float4 t0 = *(const float4*)&th_s[ik][ty * 8];
            float4 t1 = *(const float4*)&th_s[ik][ty * 8 + 4];
            float xr[4] = {xv.x, xv.y, xv.z, xv.w};
            float tr[8] = {t0.x, t0.y, t0.z, t0.w, t1.x, t1.y, t1.z, t1.w};
            #pragma unroll
            for (int nn = 0; nn < 4; nn++)
                #pragma unroll
                for (int oo = 0; oo < 8; oo++)
                    acc[nn][oo] = fmaf(xr[nn], tr[oo], acc[nn][oo]);
        }
    }

    const int o0 = ty * 8;
    #pragma unroll
    for (int oo = 0; oo < 8; oo++) {
        int o = o0 + oo;
        float v0 = acc[0][oo] + bias_s[o];
        float v1 = acc[1][oo] + bias_s[o];
        float v2 = acc[2][oo] + bias_s[o];
        float v3 = acc[3][oo] + bias_s[o];
        if (o < CIN) {
            float4 r = *(const float4*)&X[((size_t)(bb * CIN + o) * T_ + t) * N_ + n0 + tx * 4];
            v0 += r.x; v1 += r.y; v2 += r.z; v3 += r.w;
        }
        float4 w = make_float4(fmaxf(v0, 0.f), fmaxf(v1, 0.f),
                               fmaxf(v2, 0.f), fmaxf(v3, 0.f));
        *(float4*)&out[((size_t)(bb * COUT + o) * T_ + t) * N_ + n0 + tx * 4] = w;
    }
}

extern "C" void kernel_launch(void* const* d_in, const int* in_sizes, int n_in,
                              void* d_out, int out_size)
{
    const float* x     = (const float*)d_in[0];  // (32,32,12,1024)
    const float* Lk    = (const float*)d_in[1];  // (3,1024,1024)
    const float* theta = (const float*)d_in[2];  // (32,64,3)
    const float* bias  = (const float*)d_in[3];  // (1,64,1,1)
    float* out = (float*)d_out;                  // (32,64,12,1024)

    static bool attr_done = false;
    if (!attr_done) {
        cudaFuncSetAttribute(stage1_mma,
                             cudaFuncAttributeMaxDynamicSharedMemorySize, S1_SMEM);
        attr_done = true;
    }

    split_x<<<(R_ * N_) / (256 * 4), 256>>>(x);
    split_l<<<(KS * N_ * N_) / (256 * 4), 256>>>(Lk);

    dim3 g1(N_ / 256, R_ / 128, KS);   // (4, 96, 3)
    stage1_mma<<<g1, 256, S1_SMEM>>>();

    dim3 g2(N_ / 128, T_, B_);         // (8, 12, 32)
    stage2_fused<<<g2, 256>>>(x, theta, bias, out);
}

// round 4
// speedup vs baseline: 1.9816x; 1.0079x over previous
#include <cuda_runtime.h>
#include <cuda_bf16.h>
#include <cstdint>

// Problem dims (fixed by the dataset)
#define B_   32
#define CIN  32
#define T_   12
#define N_   1024
#define KS   3
#define COUT 64
#define R_   (B_ * CIN * T_)   // 12288

// Scratch (__device__ globals; no allocations allowed)
__device__ float         g_xc [(size_t)KS * R_ * N_];
__device__ __nv_bfloat16 g_xhi[(size_t)R_ * N_];
__device__ __nv_bfloat16 g_xlo[(size_t)R_ * N_];
__device__ __nv_bfloat16 g_lhi[(size_t)KS * N_ * N_];
__device__ __nv_bfloat16 g_llo[(size_t)KS * N_ * N_];

__device__ __forceinline__ uint32_t smem_u32(const void* p) {
    uint32_t a;
    asm("{ .reg .u64 t; cvta.to.shared.u64 t, %1; cvt.u32.u64 %0, t; }"
        : "=r"(a) : "l"(p));
    return a;
}
__device__ __forceinline__ void cp16(uint32_t dst, const void* src) {
    asm volatile("cp.async.cg.shared.global [%0], [%1], 16;" :: "r"(dst), "l"(src));
}
#define CP_COMMIT() asm volatile("cp.async.commit_group;" ::: "memory")
#define CP_WAIT(n)  asm volatile("cp.async.wait_group %0;" :: "n"(n) : "memory")

__device__ __forceinline__ void ldmx4(uint32_t* r, uint32_t addr) {
    asm volatile("ldmatrix.sync.aligned.m8n8.x4.shared.b16 {%0,%1,%2,%3}, [%4];"
                 : "=r"(r[0]), "=r"(r[1]), "=r"(r[2]), "=r"(r[3]) : "r"(addr));
}

// D += A*B, m16n8k16, bf16 in / fp32 acc
#define MMA_BF16(d, a, b0, b1)                                                \
    asm volatile("mma.sync.aligned.m16n8k16.row.col.f32.bf16.bf16.f32 "       \
                 "{%0,%1,%2,%3}, {%4,%5,%6,%7}, {%8,%9}, {%0,%1,%2,%3};"      \
                 : "+f"((d)[0]), "+f"((d)[1]), "+f"((d)[2]), "+f"((d)[3])     \
                 : "r"((a)[0]), "r"((a)[1]), "r"((a)[2]), "r"((a)[3]),        \
                   "r"(b0), "r"(b1))

// ---------------------------------------------------------------------------
// fp32 -> bf16 hi + lo residual splits
// ---------------------------------------------------------------------------
__global__ __launch_bounds__(256) void split_x(const float* __restrict__ src) {
    size_t i = ((size_t)blockIdx.x * 256 + threadIdx.x) * 4;
    float4 v = *(const float4*)(src + i);
    float f[4] = {v.x, v.y, v.z, v.w};
    __nv_bfloat16 h[4], l[4];
    #pragma unroll
    for (int j = 0; j < 4; j++) {
        h[j] = __float2bfloat16(f[j]);
        l[j] = __float2bfloat16(f[j] - __bfloat162float(h[j]));
    }
    *(__nv_bfloat162*)(g_xhi + i)     = __halves2bfloat162(h[0], h[1]);
    *(__nv_bfloat162*)(g_xhi + i + 2) = __halves2bfloat162(h[2], h[3]);
    *(__nv_bfloat162*)(g_xlo + i)     = __halves2bfloat162(l[0], l[1]);
    *(__nv_bfloat162*)(g_xlo + i + 2) = __halves2bfloat162(l[2], l[3]);
}
__global__ __launch_bounds__(256) void split_l(const float* __restrict__ src) {
    size_t i = ((size_t)blockIdx.x * 256 + threadIdx.x) * 4;
    float4 v = *(const float4*)(src + i);
    float f[4] = {v.x, v.y, v.z, v.w};
    __nv_bfloat16 h[4], l[4];
    #pragma unroll
    for (int j = 0; j < 4; j++) {
        h[j] = __float2bfloat16(f[j]);
        l[j] = __float2bfloat16(f[j] - __bfloat162float(h[j]));
    }
    *(__nv_bfloat162*)(g_lhi + i)     = __halves2bfloat162(h[0], h[1]);
    *(__nv_bfloat162*)(g_lhi + i + 2) = __halves2bfloat162(h[2], h[3]);
    *(__nv_bfloat162*)(g_llo + i)     = __halves2bfloat162(l[0], l[1]);
    *(__nv_bfloat162*)(g_llo + i + 2) = __halves2bfloat162(l[2], l[3]);
}

// ---------------------------------------------------------------------------
// Stage 1: x_c[k][r][n] = sum_m X[r][m]*Lk[k][n][m]  via mma.sync bf16 x3
// CTA tile 128(M) x 256(N), kc=32, 3-stage cp.async pipeline, ldmatrix frags.
// Smem rows padded to 80B -> conflict-free.
// ---------------------------------------------------------------------------
#define KC        32
#define STG_A_H   0
#define STG_A_L   10240
#define STG_B_H   20480
#define STG_B_L   40960
#define STG_STRIDE 61440
#define NSTAGE    3
#define S1_SMEM   (NSTAGE * STG_STRIDE)   // 180 KB

__global__ __launch_bounds__(256, 1) void stage1_mma() {
    extern __shared__ char smem[];
    const uint32_t sb = smem_u32(smem);

    const int tid  = threadIdx.x;
    const int lane = tid & 31;
    const int wid  = tid >> 5;
    const int wr   = wid >> 2;    // warp row 0..1 (64 rows each)
    const int wc   = wid & 3;     // warp col 0..3 (64 cols each)
    const int gid  = lane >> 2;
    const int tig  = lane & 3;

    const int kz    = blockIdx.z;
    const int rBase = blockIdx.y * 128;
    const int nBase = blockIdx.x * 256;

    const __nv_bfloat16* Ah = g_xhi + (size_t)rBase * N_;
    const __nv_bfloat16* Al = g_xlo + (size_t)rBase * N_;
    const __nv_bfloat16* Bh = g_lhi + ((size_t)kz * N_ + nBase) * N_;
    const __nv_bfloat16* Bl = g_llo + ((size_t)kz * N_ + nBase) * N_;

    // per-lane ldmatrix address components (row stride 80B)
    //   A x4: m0=rows0-7,k0-7; m1=rows8-15,k0-7; m2=rows0-7,k8-15; m3=rows8-15,k8-15
    const uint32_t aRowOff = (uint32_t)(lane & 15) * 80 + (uint32_t)(lane >> 4) * 16;
    //   B x4: m0=n0-7,k0-7; m1=n0-7,k8-15; m2=n8-15,k0-7; m3=n8-15,k8-15
    const uint32_t bRowOff = (uint32_t)((lane & 7) + ((lane >> 4) << 3)) * 80
                           + (uint32_t)((lane >> 3) & 1) * 16;
    const uint32_t aWarp = (uint32_t)(wr * 64) * 80;
    const uint32_t bWarp = (uint32_t)(wc * 64) * 80;

    auto issue = [&](int c) {
        const uint32_t stg = sb + (uint32_t)(c % NSTAGE) * STG_STRIDE;
        const int kofs = c * KC;
        #pragma unroll
        for (int j = 0; j < 12; j++) {
            const int idx = j * 256 + tid;
            if (j < 2) {
                int q = idx, row = q >> 2, c16 = q & 3;
                cp16(stg + STG_A_H + row * 80 + c16 * 16,
                     Ah + (size_t)row * N_ + kofs + c16 * 8);
            } else if (j < 4) {
                int q = idx - 512, row = q >> 2, c16 = q & 3;
                cp16(stg + STG_A_L + row * 80 + c16 * 16,
                     Al + (size_t)row * N_ + kofs + c16 * 8);
            } else if (j < 8) {
                int q = idx - 1024, row = q >> 2, c16 = q & 3;
                cp16(stg + STG_B_H + row * 80 + c16 * 16,
                     Bh + (size_t)row * N_ + kofs + c16 * 8);
            } else {
                int q = idx - 2048, row = q >> 2, c16 = q & 3;
                cp16(stg + STG_B_L + row * 80 + c16 * 16,
                     Bl + (size_t)row * N_ + kofs + c16 * 8);
            }
        }
        CP_COMMIT();
    };

    float acc[4][8][4];
    #pragma unroll
    for (int mt = 0; mt < 4; mt++)
        #pragma unroll
        for (int nt = 0; nt < 8; nt++)
            #pragma unroll
            for (int q = 0; q < 4; q++) acc[mt][nt][q] = 0.0f;

    issue(0); issue(1); issue(2);

    const int NCHUNK = N_ / KC;   // 32
    for (int c = 0; c < NCHUNK; c++) {
        if (c < NCHUNK - 2)      CP_WAIT(2);
        else if (c == NCHUNK - 2) CP_WAIT(1);
        else                      CP_WAIT(0);
        __syncthreads();

        const uint32_t stg = sb + (uint32_t)(c % NSTAGE) * STG_STRIDE;
        const uint32_t sAh = stg + STG_A_H + aWarp + aRowOff;
        const uint32_t sAl = stg + STG_A_L + aWarp + aRowOff;
        const uint32_t sBh = stg + STG_B_H + bWarp + bRowOff;
        const uint32_t sBl = stg + STG_B_L + bWarp + bRowOff;

        #pragma unroll
        for (int kst = 0; kst < 2; kst++) {
            const uint32_t kb = kst * 32;

            uint32_t ah[4][4], al[4][4];
            #pragma unroll
            for (int mt = 0; mt < 4; mt++) {
                ldmx4(ah[mt], sAh + (uint32_t)mt * (16 * 80) + kb);
                ldmx4(al[mt], sAl + (uint32_t)mt * (16 * 80) + kb);
            }

            #pragma unroll
            for (int np = 0; np < 4; np++) {       // n-pairs: nt = 2np, 2np+1
                uint32_t bh[4], bl[4];
                ldmx4(bh, sBh + (uint32_t)np * (16 * 80) + kb);
                ldmx4(bl, sBl + (uint32_t)np * (16 * 80) + kb);

                // pass-major: reuse distance 8 per accumulator
                #pragma unroll
                for (int mt = 0; mt < 4; mt++) {
                    MMA_BF16(acc[mt][2 * np],     ah[mt], bh[0], bh[1]);
                    MMA_BF16(acc[mt][2 * np + 1], ah[mt], bh[2], bh[3]);
                }
                #pragma unroll
                for (int mt = 0; mt < 4; mt++) {
                    MMA_BF16(acc[mt][2 * np],     ah[mt], bl[0], bl[1]);
                    MMA_BF16(acc[mt][2 * np + 1], ah[mt], bl[2], bl[3]);
                }
                #pragma unroll
                for (int mt = 0; mt < 4; mt++) {
                    MMA_BF16(acc[mt][2 * np],     al[mt], bh[0], bh[1]);
                    MMA_BF16(acc[mt][2 * np + 1], al[mt], bh[2], bh[3]);
                }
            }
        }
        __syncthreads();
        if (c + NSTAGE < NCHUNK) issue(c + NSTAGE);
    }

    // epilogue: fp32 acc -> g_xc
    float* C = g_xc + (size_t)kz * R_ * N_;
    const int rw = rBase + wr * 64;
    const int cw = nBase + wc * 64;
    #pragma unroll
    for (int mt = 0; mt < 4; mt++) {
        #pragma unroll
        for (int nt = 0; nt < 8; nt++) {
            const int r0 = rw + mt * 16 + gid;
            const int c0 = cw + nt * 8 + tig * 2;
            float2 v01 = make_float2(acc[mt][nt][0], acc[mt][nt][1]);
            float2 v23 = make_float2(acc[mt][nt][2], acc[mt][nt][3]);
            *(float2*)&C[(size_t)r0 * N_ + c0]       = v01;
            *(float2*)&C[(size_t)(r0 + 8) * N_ + c0] = v23;
        }
    }
}

// ---------------------------------------------------------------------------
// Stage 2 (unchanged control): out = relu(theta-contraction + bias + residual)
// ---------------------------------------------------------------------------
__global__ __launch_bounds__(256) void stage2_fused(
    const float* __restrict__ X,
    const float* __restrict__ theta,
    const float* __restrict__ bias,
    float* __restrict__ out)
{
    const int n0 = blockIdx.x * 128;
    const int t  = blockIdx.y;
    const int bb = blockIdx.z;

    __shared__ float th_s[96][64];
    __shared__ float xs[32][128];
    __shared__ float bias_s[64];

    const int tid = threadIdx.x;
    const int tx  = tid % 32;
    const int ty  = tid / 32;

    for (int idx = tid; idx < 96 * 64; idx += 256) {
        int ik = idx / 64, o = idx % 64;
        int k = ik / 32, i = ik % 32;
        th_s[ik][o] = theta[i * (COUT * KS) + o * KS + k];
    }
    if (tid < 64) bias_s[tid] = bias[tid];

    float acc[4][8];
    #pragma unroll
    for (int nn = 0; nn < 4; nn++)
        #pragma unroll
        for (int oo = 0; oo < 8; oo++) acc[nn][oo] = 0.0f;

    for (int c = 0; c < KS; c++) {
        __syncthreads();
        const float* src = g_xc + (size_t)c * R_ * N_;
        #pragma unroll
        for (int rep = 0; rep < 4; rep++) {
            int idx = rep * 256 + tid;
            int rr  = idx / 32;
            int c4  = idx % 32;
            float4 v = *(const float4*)&src[((size_t)(bb * CIN + rr) * T_ + t) * N_ + n0 + c4 * 4];
            *(float4*)&xs[rr][c4 * 4] = v;
        }
        __syncthreads();

        #pragma unroll
        for (int kk = 0; kk < 32; kk++) {
            int ik = c * 32 + kk;
            float4 xv = *(const float4*)&xs[kk][tx * 4];
            float4 t0 = *(const float4*)&th_s[ik][ty * 8];
            float4 t1 = *(const float4*)&th_s[ik][ty * 8 + 4];
            float xr[4] = {xv.x, xv.y, xv.z, xv.w};
            float tr[8] = {t0.x, t0.y, t0.z, t0.w, t1.x, t1.y, t1.z, t1.w};
            #pragma unroll
            for (int nn = 0; nn < 4; nn++)
                #pragma unroll
                for (int oo = 0; oo < 8; oo++)
                    acc[nn][oo] = fmaf(xr[nn], tr[oo], acc[nn][oo]);
        }
    }

    const int o0 = ty * 8;
    #pragma unroll
    for (int oo = 0; oo < 8; oo++) {
        int o = o0 + oo;
        float v0 = acc[0][oo] + bias_s[o];
        float v1 = acc[1][oo] + bias_s[o];
        float v2 = acc[2][oo] + bias_s[o];
        float v3 = acc[3][oo] + bias_s[o];
        if (o < CIN) {
            float4 r = *(const float4*)&X[((size_t)(bb * CIN + o) * T_ + t) * N_ + n0 + tx * 4];
            v0 += r.x; v1 += r.y; v2 += r.z; v3 += r.w;
        }
        float4 w = make_float4(fmaxf(v0, 0.f), fmaxf(v1, 0.f),
                               fmaxf(v2, 0.f), fmaxf(v3, 0.f));
        *(float4*)&out[((size_t)(bb * COUT + o) * T_ + t) * N_ + n0 + tx * 4] = w;
    }
}

extern "C" void kernel_launch(void* const* d_in, const int* in_sizes, int n_in,
                              void* d_out, int out_size)
{
    const float* x     = (const float*)d_in[0];
    const float* Lk    = (const float*)d_in[1];
    const float* theta = (const float*)d_in[2];
    const float* bias  = (const float*)d_in[3];
    float* out = (float*)d_out;

    static bool attr_done = false;
    if (!attr_done) {
        cudaFuncSetAttribute(stage1_mma,
                             cudaFuncAttributeMaxDynamicSharedMemorySize, S1_SMEM);
        attr_done = true;
    }

    split_x<<<(R_ * N_) / (256 * 4), 256>>>(x);
    split_l<<<(KS * N_ * N_) / (256 * 4), 256>>>(Lk);

    dim3 g1(N_ / 256, R_ / 128, KS);   // (4, 96, 3)
    stage1_mma<<<g1, 256, S1_SMEM>>>();

    dim3 g2(N_ / 128, T_, B_);         // (8, 12, 32)
    stage2_fused<<<g2, 256>>>(x, theta, bias, out);
}

// round 5
// speedup vs baseline: 2.6731x; 1.3490x over previous
#include <cuda_runtime.h>
#include <cuda_fp16.h>
#include <cstdint>

// Problem dims (fixed by the dataset)
#define B_   32
#define CIN  32
#define T_   12
#define N_   1024
#define KS   3
#define COUT 64
#define R_   (B_ * CIN * T_)   // 12288

// Scratch (__device__ globals; no allocations allowed)
__device__ __half g_xc [(size_t)KS * R_ * N_];     // 75.5 MB fp16, scaled x32
__device__ __half g_xhi[(size_t)R_ * N_];          // fp16(x)
__device__ __half g_lhi[(size_t)KS * N_ * N_];     // fp16(32*Lk)
__device__ __half g_llo[(size_t)KS * N_ * N_];     // fp16(32*Lk - hi)

__device__ __forceinline__ uint32_t smem_u32(const void* p) {
    uint32_t a;
    asm("{ .reg .u64 t; cvta.to.shared.u64 t, %1; cvt.u32.u64 %0, t; }"
        : "=r"(a) : "l"(p));
    return a;
}
__device__ __forceinline__ void cp16(uint32_t dst, const void* src) {
    asm volatile("cp.async.cg.shared.global [%0], [%1], 16;" :: "r"(dst), "l"(src));
}
#define CP_COMMIT() asm volatile("cp.async.commit_group;" ::: "memory")
#define CP_WAIT(n)  asm volatile("cp.async.wait_group %0;" :: "n"(n) : "memory")

__device__ __forceinline__ void ldmx4(uint32_t* r, uint32_t addr) {
    asm volatile("ldmatrix.sync.aligned.m8n8.x4.shared.b16 {%0,%1,%2,%3}, [%4];"
                 : "=r"(r[0]), "=r"(r[1]), "=r"(r[2]), "=r"(r[3]) : "r"(addr));
}

// D += A*B, m16n8k16, fp16 in / fp32 acc
#define MMA_F16(d, a, b0, b1)                                                 \
    asm volatile("mma.sync.aligned.m16n8k16.row.col.f32.f16.f16.f32 "         \
                 "{%0,%1,%2,%3}, {%4,%5,%6,%7}, {%8,%9}, {%0,%1,%2,%3};"      \
                 : "+f"((d)[0]), "+f"((d)[1]), "+f"((d)[2]), "+f"((d)[3])     \
                 : "r"((a)[0]), "r"((a)[1]), "r"((a)[2]), "r"((a)[3]),        \
                   "r"(b0), "r"(b1))

// ---------------------------------------------------------------------------
// fp32 -> fp16 conversions (x: hi only; Lk: scaled x32, hi + lo residual)
// ---------------------------------------------------------------------------
__global__ __launch_bounds__(256) void split_x(const float* __restrict__ src) {
    size_t i = ((size_t)blockIdx.x * 256 + threadIdx.x) * 4;
    float4 v = *(const float4*)(src + i);
    __half2 h01 = __floats2half2_rn(v.x, v.y);
    __half2 h23 = __floats2half2_rn(v.z, v.w);
    *(__half2*)(g_xhi + i)     = h01;
    *(__half2*)(g_xhi + i + 2) = h23;
}
__global__ __launch_bounds__(256) void split_l(const float* __restrict__ src) {
    size_t i = ((size_t)blockIdx.x * 256 + threadIdx.x) * 4;
    float4 v = *(const float4*)(src + i);
    float f[4] = {v.x * 32.0f, v.y * 32.0f, v.z * 32.0f, v.w * 32.0f};
    __half h[4], l[4];
    #pragma unroll
    for (int j = 0; j < 4; j++) {
        h[j] = __float2half_rn(f[j]);
        l[j] = __float2half_rn(f[j] - __half2float(h[j]));
    }
    *(__half2*)(g_lhi + i)     = __halves2half2(h[0], h[1]);
    *(__half2*)(g_lhi + i + 2) = __halves2half2(h[2], h[3]);
    *(__half2*)(g_llo + i)     = __halves2half2(l[0], l[1]);
    *(__half2*)(g_llo + i + 2) = __halves2half2(l[2], l[3]);
}

// ---------------------------------------------------------------------------
// Stage 1: xc'[k][r][n] = sum_m x[r][m] * (32*Lk[k][n][m]), fp16 2-pass.
// CTA tile 256(M) x 128(N), kc=32, 4-stage cp.async pipeline, ldmatrix.
// 8 warps = 4 warp-rows x 2 warp-cols, each 64x64 (acc 128 fp32 regs).
// Smem rows padded to 80B -> conflict-free ldmatrix.
// ---------------------------------------------------------------------------
#define KC         32
#define STG_A      0                       // 256 rows * 80B = 20480
#define STG_BH     20480                   // 128 rows * 80B = 10240
#define STG_BL     30720                   // 10240
#define STG_STRIDE 40960
#define NSTAGE     4
#define S1_SMEM    (NSTAGE * STG_STRIDE)   // 160 KB

__global__ __launch_bounds__(256, 1) void stage1_mma() {
    extern __shared__ char smem[];
    const uint32_t sb = smem_u32(smem);

    const int tid  = threadIdx.x;
    const int lane = tid & 31;
    const int wid  = tid >> 5;
    const int wr   = wid >> 1;    // warp row 0..3 (64 rows each)
    const int wc   = wid & 1;     // warp col 0..1 (64 cols each)
    const int gid  = lane >> 2;
    const int tig  = lane & 3;

    const int kz    = blockIdx.z;
    const int rBase = blockIdx.y * 256;
    const int nBase = blockIdx.x * 128;

    const __half* Ax = g_xhi + (size_t)rBase * N_;
    const __half* Bh = g_lhi + ((size_t)kz * N_ + nBase) * N_;
    const __half* Bl = g_llo + ((size_t)kz * N_ + nBase) * N_;

    // ldmatrix per-lane address components (row stride 80B)
    const uint32_t aRowOff = (uint32_t)(lane & 15) * 80 + (uint32_t)(lane >> 4) * 16;
    const uint32_t bRowOff = (uint32_t)((lane & 7) + ((lane >> 4) << 3)) * 80
                           + (uint32_t)((lane >> 3) & 1) * 16;
    const uint32_t aWarp = (uint32_t)(wr * 64) * 80;
    const uint32_t bWarp = (uint32_t)(wc * 64) * 80;

    auto issue = [&](int c) {
        const uint32_t stg = sb + (uint32_t)(c % NSTAGE) * STG_STRIDE;
        const int kofs = c * KC;
        #pragma unroll
        for (int j = 0; j < 8; j++) {
            const int idx = j * 256 + tid;
            if (j < 4) {                      // A: 1024 x 16B
                int row = idx >> 2, c16 = idx & 3;
                cp16(stg + STG_A + row * 80 + c16 * 16,
                     Ax + (size_t)row * N_ + kofs + c16 * 8);
            } else if (j < 6) {               // B hi: 512 x 16B
                int q = idx - 1024, row = q >> 2, c16 = q & 3;
                cp16(stg + STG_BH + row * 80 + c16 * 16,
                     Bh + (size_t)row * N_ + kofs + c16 * 8);
            } else {                          // B lo: 512 x 16B
                int q = idx - 1536, row = q >> 2, c16 = q & 3;
                cp16(stg + STG_BL + row * 80 + c16 * 16,
                     Bl + (size_t)row * N_ + kofs + c16 * 8);
            }
        }
        CP_COMMIT();
    };

    float acc[4][8][4];
    #pragma unroll
    for (int mt = 0; mt < 4; mt++)
        #pragma unroll
        for (int nt = 0; nt < 8; nt++)
            #pragma unroll
            for (int q = 0; q < 4; q++) acc[mt][nt][q] = 0.0f;

    issue(0); issue(1); issue(2);

    const int NCHUNK = N_ / KC;   // 32
    for (int c = 0; c < NCHUNK; c++) {
        if (c < NCHUNK - 2)       CP_WAIT(2);
        else if (c == NCHUNK - 2) CP_WAIT(1);
        else                      CP_WAIT(0);
        __syncthreads();
        if (c + 3 < NCHUNK) issue(c + 3);   // stage (c+3)%4 is free

        const uint32_t stg = sb + (uint32_t)(c % NSTAGE) * STG_STRIDE;
        const uint32_t sA  = stg + STG_A  + aWarp + aRowOff;
        const uint32_t sBh = stg + STG_BH + bWarp + bRowOff;
        const uint32_t sBl = stg + STG_BL + bWarp + bRowOff;

        #pragma unroll
        for (int kst = 0; kst < 2; kst++) {
            const uint32_t kb = kst * 32;

            uint32_t ax[4][4];
            #pragma unroll
            for (int mt = 0; mt < 4; mt++)
                ldmx4(ax[mt], sA + (uint32_t)mt * (16 * 80) + kb);

            #pragma unroll
            for (int np = 0; np < 4; np++) {       // nt = 2np, 2np+1
                uint32_t bh[4], bl[4];
                ldmx4(bh, sBh + (uint32_t)np * (16 * 80) + kb);
                ldmx4(bl, sBl + (uint32_t)np * (16 * 80) + kb);

                #pragma unroll
                for (int mt = 0; mt < 4; mt++) {
                    MMA_F16(acc[mt][2 * np],     ax[mt], bh[0], bh[1]);
                    MMA_F16(acc[mt][2 * np + 1], ax[mt], bh[2], bh[3]);
                }
                #pragma unroll
                for (int mt = 0; mt < 4; mt++) {
                    MMA_F16(acc[mt][2 * np],     ax[mt], bl[0], bl[1]);
                    MMA_F16(acc[mt][2 * np + 1], ax[mt], bl[2], bl[3]);
                }
            }
        }
    }

    // epilogue: fp32 acc -> fp16 g_xc (values scaled x32; theta unscales)
    __half* C = g_xc + (size_t)kz * R_ * N_;
    const int rw = rBase + wr * 64;
    const int cw = nBase + wc * 64;
    #pragma unroll
    for (int mt = 0; mt < 4; mt++) {
        #pragma unroll
        for (int nt = 0; nt < 8; nt++) {
            const int r0 = rw + mt * 16 + gid;
            const int c0 = cw + nt * 8 + tig * 2;
            __half2 v01 = __floats2half2_rn(acc[mt][nt][0], acc[mt][nt][1]);
            __half2 v23 = __floats2half2_rn(acc[mt][nt][2], acc[mt][nt][3]);
            *(__half2*)&C[(size_t)r0 * N_ + c0]       = v01;
            *(__half2*)&C[(size_t)(r0 + 8) * N_ + c0] = v23;
        }
    }
}

// ---------------------------------------------------------------------------
// Stage 2: out = relu((theta/32)-contraction of fp16 xc' + bias + residual)
// ---------------------------------------------------------------------------
__global__ __launch_bounds__(256) void stage2_fused(
    const float* __restrict__ X,
    const float* __restrict__ theta,
    const float* __restrict__ bias,
    float* __restrict__ out)
{
    const int n0 = blockIdx.x * 128;
    const int t  = blockIdx.y;
    const int bb = blockIdx.z;

    __shared__ float th_s[96][64];
    __shared__ float xs[32][128];
    __shared__ float bias_s[64];

    const int tid = threadIdx.x;
    const int tx  = tid % 32;
    const int ty  = tid / 32;

    for (int idx = tid; idx < 96 * 64; idx += 256) {
        int ik = idx / 64, o = idx % 64;
        int k = ik / 32, i = ik % 32;
        th_s[ik][o] = theta[i * (COUT * KS) + o * KS + k] * (1.0f / 32.0f);
    }
    if (tid < 64) bias_s[tid] = bias[tid];

    float acc[4][8];
    #pragma unroll
    for (int nn = 0; nn < 4; nn++)
        #pragma unroll
        for (int oo = 0; oo < 8; oo++) acc[nn][oo] = 0.0f;

    for (int c = 0; c < KS; c++) {
        __syncthreads();
        const __half* src = g_xc + (size_t)c * R_ * N_;
        #pragma unroll
        for (int rep = 0; rep < 4; rep++) {
            int idx = rep * 256 + tid;
            int rr  = idx / 32;
            int c4  = idx % 32;
            uint2 raw = *(const uint2*)&src[((size_t)(bb * CIN + rr) * T_ + t) * N_ + n0 + c4 * 4];
            __half2 h01 = *reinterpret_cast<__half2*>(&raw.x);
            __half2 h23 = *reinterpret_cast<__half2*>(&raw.y);
            float2 f01 = __half22float2(h01);
            float2 f23 = __half22float2(h23);
            *(float4*)&xs[rr][c4 * 4] = make_float4(f01.x, f01.y, f23.x, f23.y);
        }
        __syncthreads();

        #pragma unroll
        for (int kk = 0; kk < 32; kk++) {
            int ik = c * 32 + kk;
            float4 xv = *(const float4*)&xs[kk][tx * 4];
            float4 t0 = *(const float4*)&th_s[ik][ty * 8];
            float4 t1 = *(const float4*)&th_s[ik][ty * 8 + 4];
            float xr[4] = {xv.x, xv.y, xv.z, xv.w};
            float tr[8] = {t0.x, t0.y, t0.z, t0.w, t1.x, t1.y, t1.z, t1.w};
            #pragma unroll
            for (int nn = 0; nn < 4; nn++)
                #pragma unroll
                for (int oo = 0; oo < 8; oo++)
                    acc[nn][oo] = fmaf(xr[nn], tr[oo], acc[nn][oo]);
        }
    }

    const int o0 = ty * 8;
    #pragma unroll
    for (int oo = 0; oo < 8; oo++) {
        int o = o0 + oo;
        float v0 = acc[0][oo] + bias_s[o];
        float v1 = acc[1][oo] + bias_s[o];
        float v2 = acc[2][oo] + bias_s[o];
        float v3 = acc[3][oo] + bias_s[o];
        if (o < CIN) {
            float4 r = *(const float4*)&X[((size_t)(bb * CIN + o) * T_ + t) * N_ + n0 + tx * 4];
            v0 += r.x; v1 += r.y; v2 += r.z; v3 += r.w;
        }
        float4 w = make_float4(fmaxf(v0, 0.f), fmaxf(v1, 0.f),
                               fmaxf(v2, 0.f), fmaxf(v3, 0.f));
        *(float4*)&out[((size_t)(bb * COUT + o) * T_ + t) * N_ + n0 + tx * 4] = w;
    }
}

extern "C" void kernel_launch(void* const* d_in, const int* in_sizes, int n_in,
                              void* d_out, int out_size)
{
    const float* x     = (const float*)d_in[0];
    const float* Lk    = (const float*)d_in[1];
    const float* theta = (const float*)d_in[2];
    const float* bias  = (const float*)d_in[3];
    float* out = (float*)d_out;

    static bool attr_done = false;
    if (!attr_done) {
        cudaFuncSetAttribute(stage1_mma,
                             cudaFuncAttributeMaxDynamicSharedMemorySize, S1_SMEM);
        attr_done = true;
    }

    split_x<<<(R_ * N_) / (256 * 4), 256>>>(x);
    split_l<<<(KS * N_ * N_) / (256 * 4), 256>>>(Lk);

    dim3 g1(N_ / 128, R_ / 256, KS);   // (8, 48, 3)
    stage1_mma<<<g1, 256, S1_SMEM>>>();

    dim3 g2(N_ / 128, T_, B_);         // (8, 12, 32)
    stage2_fused<<<g2, 256>>>(x, theta, bias, out);
}

// round 6
// speedup vs baseline: 3.7415x; 1.3997x over previous
#include <cuda_runtime.h>
#include <cuda_fp16.h>
#include <cstdint>

// Problem dims (fixed by the dataset)
#define B_   32
#define CIN  32
#define T_   12
#define N_   1024
#define KS   3
#define COUT 64
#define R_   (B_ * CIN * T_)   // 12288

// Scratch (__device__ globals; no allocations allowed)
__device__ __half g_xc [(size_t)KS * R_ * N_];     // 75.5 MB fp16
__device__ __half g_xhi[(size_t)R_ * N_];          // fp16(x)
__device__ __half g_lhi[(size_t)KS * N_ * N_];     // fp16(Lk)

__device__ __forceinline__ uint32_t smem_u32(const void* p) {
    uint32_t a;
    asm("{ .reg .u64 t; cvta.to.shared.u64 t, %1; cvt.u32.u64 %0, t; }"
        : "=r"(a) : "l"(p));
    return a;
}
__device__ __forceinline__ void cp16(uint32_t dst, const void* src) {
    asm volatile("cp.async.cg.shared.global [%0], [%1], 16;" :: "r"(dst), "l"(src));
}
#define CP_COMMIT() asm volatile("cp.async.commit_group;" ::: "memory")
#define CP_WAIT(n)  asm volatile("cp.async.wait_group %0;" :: "n"(n) : "memory")

__device__ __forceinline__ void ldmx4(uint32_t* r, uint32_t addr) {
    asm volatile("ldmatrix.sync.aligned.m8n8.x4.shared.b16 {%0,%1,%2,%3}, [%4];"
                 : "=r"(r[0]), "=r"(r[1]), "=r"(r[2]), "=r"(r[3]) : "r"(addr));
}

// D += A*B, m16n8k16, fp16 in / fp32 acc
#define MMA_F16(d, a, b0, b1)                                                 \
    asm volatile("mma.sync.aligned.m16n8k16.row.col.f32.f16.f16.f32 "         \
                 "{%0,%1,%2,%3}, {%4,%5,%6,%7}, {%8,%9}, {%0,%1,%2,%3};"      \
                 : "+f"((d)[0]), "+f"((d)[1]), "+f"((d)[2]), "+f"((d)[3])     \
                 : "r"((a)[0]), "r"((a)[1]), "r"((a)[2]), "r"((a)[3]),        \
                   "r"(b0), "r"(b1))

// ---------------------------------------------------------------------------
// fp32 -> fp16 converts
// ---------------------------------------------------------------------------
__global__ __launch_bounds__(256) void split_x(const float* __restrict__ src) {
    size_t i = ((size_t)blockIdx.x * 256 + threadIdx.x) * 4;
    float4 v = *(const float4*)(src + i);
    *(__half2*)(g_xhi + i)     = __floats2half2_rn(v.x, v.y);
    *(__half2*)(g_xhi + i + 2) = __floats2half2_rn(v.z, v.w);
}
__global__ __launch_bounds__(256) void split_l(const float* __restrict__ src) {
    size_t i = ((size_t)blockIdx.x * 256 + threadIdx.x) * 4;
    float4 v = *(const float4*)(src + i);
    *(__half2*)(g_lhi + i)     = __floats2half2_rn(v.x, v.y);
    *(__half2*)(g_lhi + i + 2) = __floats2half2_rn(v.z, v.w);
}

// ---------------------------------------------------------------------------
// Stage 1: xc[k][r][n] = sum_m x[r][m] * Lk[k][n][m], single-pass fp16 HMMA.
// CTA tile 256(M) x 128(N), kc=32, 4-stage cp.async pipeline, ldmatrix.
// 8 warps = 4 warp-rows x 2 warp-cols, each 64x64.
// Smem rows padded to 80B -> conflict-free ldmatrix.
// ---------------------------------------------------------------------------
#define KC         32
#define STG_A      0                       // 256 rows * 80B = 20480
#define STG_BH     20480                   // 128 rows * 80B = 10240
#define STG_STRIDE 30720
#define NSTAGE     4
#define S1_SMEM    (NSTAGE * STG_STRIDE)   // 120 KB

__global__ __launch_bounds__(256, 1) void stage1_mma() {
    extern __shared__ char smem[];
    const uint32_t sb = smem_u32(smem);

    const int tid  = threadIdx.x;
    const int lane = tid & 31;
    const int wid  = tid >> 5;
    const int wr   = wid >> 1;    // warp row 0..3 (64 rows each)
    const int wc   = wid & 1;     // warp col 0..1 (64 cols each)
    const int gid  = lane >> 2;
    const int tig  = lane & 3;

    const int kz    = blockIdx.z;
    const int rBase = blockIdx.y * 256;
    const int nBase = blockIdx.x * 128;

    const __half* Ax = g_xhi + (size_t)rBase * N_;
    const __half* Bh = g_lhi + ((size_t)kz * N_ + nBase) * N_;

    const uint32_t aRowOff = (uint32_t)(lane & 15) * 80 + (uint32_t)(lane >> 4) * 16;
    const uint32_t bRowOff = (uint32_t)((lane & 7) + ((lane >> 4) << 3)) * 80
                           + (uint32_t)((lane >> 3) & 1) * 16;
    const uint32_t aWarp = (uint32_t)(wr * 64) * 80;
    const uint32_t bWarp = (uint32_t)(wc * 64) * 80;

    auto issue = [&](int c) {
        const uint32_t stg = sb + (uint32_t)(c % NSTAGE) * STG_STRIDE;
        const int kofs = c * KC;
        #pragma unroll
        for (int j = 0; j < 6; j++) {
            const int idx = j * 256 + tid;
            if (j < 4) {                      // A: 1024 x 16B
                int row = idx >> 2, c16 = idx & 3;
                cp16(stg + STG_A + row * 80 + c16 * 16,
                     Ax + (size_t)row * N_ + kofs + c16 * 8);
            } else {                          // B: 512 x 16B
                int q = idx - 1024, row = q >> 2, c16 = q & 3;
                cp16(stg + STG_BH + row * 80 + c16 * 16,
                     Bh + (size_t)row * N_ + kofs + c16 * 8);
            }
        }
        CP_COMMIT();
    };

    float acc[4][8][4];
    #pragma unroll
    for (int mt = 0; mt < 4; mt++)
        #pragma unroll
        for (int nt = 0; nt < 8; nt++)
            #pragma unroll
            for (int q = 0; q < 4; q++) acc[mt][nt][q] = 0.0f;

    issue(0); issue(1); issue(2);

    const int NCHUNK = N_ / KC;   // 32
    for (int c = 0; c < NCHUNK; c++) {
        if (c < NCHUNK - 2)       CP_WAIT(2);
        else if (c == NCHUNK - 2) CP_WAIT(1);
        else                      CP_WAIT(0);
        __syncthreads();
        if (c + 3 < NCHUNK) issue(c + 3);

        const uint32_t stg = sb + (uint32_t)(c % NSTAGE) * STG_STRIDE;
        const uint32_t sA  = stg + STG_A  + aWarp + aRowOff;
        const uint32_t sB  = stg + STG_BH + bWarp + bRowOff;

        #pragma unroll
        for (int kst = 0; kst < 2; kst++) {
            const uint32_t kb = kst * 32;

            uint32_t ax[4][4];
            #pragma unroll
            for (int mt = 0; mt < 4; mt++)
                ldmx4(ax[mt], sA + (uint32_t)mt * (16 * 80) + kb);

            #pragma unroll
            for (int np = 0; np < 4; np++) {       // nt = 2np, 2np+1
                uint32_t bh[4];
                ldmx4(bh, sB + (uint32_t)np * (16 * 80) + kb);
                #pragma unroll
                for (int mt = 0; mt < 4; mt++) {
                    MMA_F16(acc[mt][2 * np],     ax[mt], bh[0], bh[1]);
                    MMA_F16(acc[mt][2 * np + 1], ax[mt], bh[2], bh[3]);
                }
            }
        }
    }

    // epilogue: fp32 acc -> fp16 g_xc
    __half* C = g_xc + (size_t)kz * R_ * N_;
    const int rw = rBase + wr * 64;
    const int cw = nBase + wc * 64;
    #pragma unroll
    for (int mt = 0; mt < 4; mt++) {
        #pragma unroll
        for (int nt = 0; nt < 8; nt++) {
            const int r0 = rw + mt * 16 + gid;
            const int c0 = cw + nt * 8 + tig * 2;
            __half2 v01 = __floats2half2_rn(acc[mt][nt][0], acc[mt][nt][1]);
            __half2 v23 = __floats2half2_rn(acc[mt][nt][2], acc[mt][nt][3]);
            *(__half2*)&C[(size_t)r0 * N_ + c0]       = v01;
            *(__half2*)&C[(size_t)(r0 + 8) * N_ + c0] = v23;
        }
    }
}

// ---------------------------------------------------------------------------
// Stage 2 (control): out = relu(theta-contraction of fp16 xc + bias + residual)
// ---------------------------------------------------------------------------
__global__ __launch_bounds__(256) void stage2_fused(
    const float* __restrict__ X,
    const float* __restrict__ theta,
    const float* __restrict__ bias,
    float* __restrict__ out)
{
    const int n0 = blockIdx.x * 128;
    const int t  = blockIdx.y;
    const int bb = blockIdx.z;

    __shared__ float th_s[96][64];
    __shared__ float xs[32][128];
    __shared__ float bias_s[64];

    const int tid = threadIdx.x;
    const int tx  = tid % 32;
    const int ty  = tid / 32;

    for (int idx = tid; idx < 96 * 64; idx += 256) {
        int ik = idx / 64, o = idx % 64;
        int k = ik / 32, i = ik % 32;
        th_s[ik][o] = theta[i * (COUT * KS) + o * KS + k];
    }
    if (tid < 64) bias_s[tid] = bias[tid];

    float acc[4][8];
    #pragma unroll
    for (int nn = 0; nn < 4; nn++)
        #pragma unroll
        for (int oo = 0; oo < 8; oo++) acc[nn][oo] = 0.0f;

    for (int c = 0; c < KS; c++) {
        __syncthreads();
        const __half* src = g_xc + (size_t)c * R_ * N_;
        #pragma unroll
        for (int rep = 0; rep < 4; rep++) {
            int idx = rep * 256 + tid;
            int rr  = idx / 32;
            int c4  = idx % 32;
            uint2 raw = *(const uint2*)&src[((size_t)(bb * CIN + rr) * T_ + t) * N_ + n0 + c4 * 4];
            __half2 h01 = *reinterpret_cast<__half2*>(&raw.x);
            __half2 h23 = *reinterpret_cast<__half2*>(&raw.y);
            float2 f01 = __half22float2(h01);
            float2 f23 = __half22float2(h23);
            *(float4*)&xs[rr][c4 * 4] = make_float4(f01.x, f01.y, f23.x, f23.y);
        }
        __syncthreads();

        #pragma unroll
        for (int kk = 0; kk < 32; kk++) {
            int ik = c * 32 + kk;
            float4 xv = *(const float4*)&xs[kk][tx * 4];
            float4 t0 = *(const float4*)&th_s[ik][ty * 8];
            float4 t1 = *(const float4*)&th_s[ik][ty * 8 + 4];
            float xr[4] = {xv.x, xv.y, xv.z, xv.w};
            float tr[8] = {t0.x, t0.y, t0.z, t0.w, t1.x, t1.y, t1.z, t1.w};
            #pragma unroll
            for (int nn = 0; nn < 4; nn++)
                #pragma unroll
                for (int oo = 0; oo < 8; oo++)
                    acc[nn][oo] = fmaf(xr[nn], tr[oo], acc[nn][oo]);
        }
    }

    const int o0 = ty * 8;
    #pragma unroll
    for (int oo = 0; oo < 8; oo++) {
        int o = o0 + oo;
        float v0 = acc[0][oo] + bias_s[o];
        float v1 = acc[1][oo] + bias_s[o];
        float v2 = acc[2][oo] + bias_s[o];
        float v3 = acc[3][oo] + bias_s[o];
        if (o < CIN) {
            float4 r = *(const float4*)&X[((size_t)(bb * CIN + o) * T_ + t) * N_ + n0 + tx * 4];
            v0 += r.x; v1 += r.y; v2 += r.z; v3 += r.w;
        }
        float4 w = make_float4(fmaxf(v0, 0.f), fmaxf(v1, 0.f),
                               fmaxf(v2, 0.f), fmaxf(v3, 0.f));
        *(float4*)&out[((size_t)(bb * COUT + o) * T_ + t) * N_ + n0 + tx * 4] = w;
    }
}

extern "C" void kernel_launch(void* const* d_in, const int* in_sizes, int n_in,
                              void* d_out, int out_size)
{
    const float* x     = (const float*)d_in[0];
    const float* Lk    = (const float*)d_in[1];
    const float* theta = (const float*)d_in[2];
    const float* bias  = (const float*)d_in[3];
    float* out = (float*)d_out;

    static bool attr_done = false;
    if (!attr_done) {
        cudaFuncSetAttribute(stage1_mma,
                             cudaFuncAttributeMaxDynamicSharedMemorySize, S1_SMEM);
        attr_done = true;
    }

    split_x<<<(R_ * N_) / (256 * 4), 256>>>(x);
    split_l<<<(KS * N_ * N_) / (256 * 4), 256>>>(Lk);

    dim3 g1(N_ / 128, R_ / 256, KS);   // (8, 48, 3)
    stage1_mma<<<g1, 256, S1_SMEM>>>();

    dim3 g2(N_ / 128, T_, B_);         // (8, 12, 32)
    stage2_fused<<<g2, 256>>>(x, theta, bias, out);
}

// round 7
// speedup vs baseline: 4.0686x; 1.0874x over previous
#include <cuda_runtime.h>
#include <cuda_fp16.h>
#include <cstdint>

// Problem dims (fixed by the dataset)
#define B_   32
#define CIN  32
#define T_   12
#define N_   1024
#define KS   3
#define COUT 64
#define R_   (B_ * CIN * T_)   // 12288

// Scratch (__device__ globals; no allocations allowed)
__device__ __half g_xc [(size_t)KS * R_ * N_];     // 75.5 MB fp16
__device__ __half g_xhi[(size_t)R_ * N_];          // fp16(x)
__device__ __half g_lhi[(size_t)KS * N_ * N_];     // fp16(Lk)

__device__ __forceinline__ uint32_t smem_u32(const void* p) {
    uint32_t a;
    asm("{ .reg .u64 t; cvta.to.shared.u64 t, %1; cvt.u32.u64 %0, t; }"
        : "=r"(a) : "l"(p));
    return a;
}
__device__ __forceinline__ void cp16(uint32_t dst, const void* src) {
    asm volatile("cp.async.cg.shared.global [%0], [%1], 16;" :: "r"(dst), "l"(src));
}
#define CP_COMMIT() asm volatile("cp.async.commit_group;" ::: "memory")
#define CP_WAIT(n)  asm volatile("cp.async.wait_group %0;" :: "n"(n) : "memory")

__device__ __forceinline__ void ldmx4(uint32_t* r, uint32_t addr) {
    asm volatile("ldmatrix.sync.aligned.m8n8.x4.shared.b16 {%0,%1,%2,%3}, [%4];"
                 : "=r"(r[0]), "=r"(r[1]), "=r"(r[2]), "=r"(r[3]) : "r"(addr));
}
__device__ __forceinline__ void ldmx4t(uint32_t* r, uint32_t addr) {
    asm volatile("ldmatrix.sync.aligned.m8n8.x4.trans.shared.b16 {%0,%1,%2,%3}, [%4];"
                 : "=r"(r[0]), "=r"(r[1]), "=r"(r[2]), "=r"(r[3]) : "r"(addr));
}

// D += A*B, m16n8k16, fp16 in / fp32 acc
#define MMA_F16(d, a, b0, b1)                                                 \
    asm volatile("mma.sync.aligned.m16n8k16.row.col.f32.f16.f16.f32 "         \
                 "{%0,%1,%2,%3}, {%4,%5,%6,%7}, {%8,%9}, {%0,%1,%2,%3};"      \
                 : "+f"((d)[0]), "+f"((d)[1]), "+f"((d)[2]), "+f"((d)[3])     \
                 : "r"((a)[0]), "r"((a)[1]), "r"((a)[2]), "r"((a)[3]),        \
                   "r"(b0), "r"(b1))

// ---------------------------------------------------------------------------
// fp32 -> fp16 converts
// ---------------------------------------------------------------------------
__global__ __launch_bounds__(256) void split_x(const float* __restrict__ src) {
    size_t i = ((size_t)blockIdx.x * 256 + threadIdx.x) * 4;
    float4 v = *(const float4*)(src + i);
    *(__half2*)(g_xhi + i)     = __floats2half2_rn(v.x, v.y);
    *(__half2*)(g_xhi + i + 2) = __floats2half2_rn(v.z, v.w);
}
__global__ __launch_bounds__(256) void split_l(const float* __restrict__ src) {
    size_t i = ((size_t)blockIdx.x * 256 + threadIdx.x) * 4;
    float4 v = *(const float4*)(src + i);
    *(__half2*)(g_lhi + i)     = __floats2half2_rn(v.x, v.y);
    *(__half2*)(g_lhi + i + 2) = __floats2half2_rn(v.z, v.w);
}

// ---------------------------------------------------------------------------
// Stage 1 (unchanged control): single-pass fp16 HMMA, 256x128 tile, 4-stage.
// ---------------------------------------------------------------------------
#define KC         32
#define STG_A      0
#define STG_BH     20480
#define STG_STRIDE 30720
#define NSTAGE     4
#define S1_SMEM    (NSTAGE * STG_STRIDE)   // 120 KB

__global__ __launch_bounds__(256, 1) void stage1_mma() {
    extern __shared__ char smem[];
    const uint32_t sb = smem_u32(smem);

    const int tid  = threadIdx.x;
    const int lane = tid & 31;
    const int wid  = tid >> 5;
    const int wr   = wid >> 1;
    const int wc   = wid & 1;
    const int gid  = lane >> 2;
    const int tig  = lane & 3;

    const int kz    = blockIdx.z;
    const int rBase = blockIdx.y * 256;
    const int nBase = blockIdx.x * 128;

    const __half* Ax = g_xhi + (size_t)rBase * N_;
    const __half* Bh = g_lhi + ((size_t)kz * N_ + nBase) * N_;

    const uint32_t aRowOff = (uint32_t)(lane & 15) * 80 + (uint32_t)(lane >> 4) * 16;
    const uint32_t bRowOff = (uint32_t)((lane & 7) + ((lane >> 4) << 3)) * 80
                           + (uint32_t)((lane >> 3) & 1) * 16;
    const uint32_t aWarp = (uint32_t)(wr * 64) * 80;
    const uint32_t bWarp = (uint32_t)(wc * 64) * 80;

    auto issue = [&](int c) {
        const uint32_t stg = sb + (uint32_t)(c % NSTAGE) * STG_STRIDE;
        const int kofs = c * KC;
        #pragma unroll
        for (int j = 0; j < 6; j++) {
            const int idx = j * 256 + tid;
            if (j < 4) {
                int row = idx >> 2, c16 = idx & 3;
                cp16(stg + STG_A + row * 80 + c16 * 16,
                     Ax + (size_t)row * N_ + kofs + c16 * 8);
            } else {
                int q = idx - 1024, row = q >> 2, c16 = q & 3;
                cp16(stg + STG_BH + row * 80 + c16 * 16,
                     Bh + (size_t)row * N_ + kofs + c16 * 8);
            }
        }
        CP_COMMIT();
    };

    float acc[4][8][4];
    #pragma unroll
    for (int mt = 0; mt < 4; mt++)
        #pragma unroll
        for (int nt = 0; nt < 8; nt++)
            #pragma unroll
            for (int q = 0; q < 4; q++) acc[mt][nt][q] = 0.0f;

    issue(0); issue(1); issue(2);

    const int NCHUNK = N_ / KC;
    for (int c = 0; c < NCHUNK; c++) {
        if (c < NCHUNK - 2)       CP_WAIT(2);
        else if (c == NCHUNK - 2) CP_WAIT(1);
        else                      CP_WAIT(0);
        __syncthreads();
        if (c + 3 < NCHUNK) issue(c + 3);

        const uint32_t stg = sb + (uint32_t)(c % NSTAGE) * STG_STRIDE;
        const uint32_t sA  = stg + STG_A  + aWarp + aRowOff;
        const uint32_t sB  = stg + STG_BH + bWarp + bRowOff;

        #pragma unroll
        for (int kst = 0; kst < 2; kst++) {
            const uint32_t kb = kst * 32;
            uint32_t ax[4][4];
            #pragma unroll
            for (int mt = 0; mt < 4; mt++)
                ldmx4(ax[mt], sA + (uint32_t)mt * (16 * 80) + kb);
            #pragma unroll
            for (int np = 0; np < 4; np++) {
                uint32_t bh[4];
                ldmx4(bh, sB + (uint32_t)np * (16 * 80) + kb);
                #pragma unroll
                for (int mt = 0; mt < 4; mt++) {
                    MMA_F16(acc[mt][2 * np],     ax[mt], bh[0], bh[1]);
                    MMA_F16(acc[mt][2 * np + 1], ax[mt], bh[2], bh[3]);
                }
            }
        }
    }

    __half* C = g_xc + (size_t)kz * R_ * N_;
    const int rw = rBase + wr * 64;
    const int cw = nBase + wc * 64;
    #pragma unroll
    for (int mt = 0; mt < 4; mt++) {
        #pragma unroll
        for (int nt = 0; nt < 8; nt++) {
            const int r0 = rw + mt * 16 + gid;
            const int c0 = cw + nt * 8 + tig * 2;
            __half2 v01 = __floats2half2_rn(acc[mt][nt][0], acc[mt][nt][1]);
            __half2 v23 = __floats2half2_rn(acc[mt][nt][2], acc[mt][nt][3]);
            *(__half2*)&C[(size_t)r0 * N_ + c0]       = v01;
            *(__half2*)&C[(size_t)(r0 + 8) * N_ + c0] = v23;
        }
    }
}

// ---------------------------------------------------------------------------
// Stage 2 (HMMA): per (b,t,n-half): D[o=64][n=512] = sum_ik th[ik][o]*xc[ik][n]
// A = theta (fp16 hi+lo, 2-pass), B = xc via ldmatrix.trans.
// 3 k-slabs cp.async'd into 3 separate smem buffers upfront.
// ---------------------------------------------------------------------------
#define XC_ROW_B   1040                 // 512 halfs + 8 pad  = 1040 bytes
#define XC_SLAB_B  (32 * XC_ROW_B)      // 33280
#define TH_ROW_B   208                  // 96 halfs + 8 pad
#define S2_TH_HI   (3 * XC_SLAB_B)      // 99840
#define S2_TH_LO   (S2_TH_HI + 64 * TH_ROW_B)   // 113152
#define S2_BIAS    (S2_TH_LO + 64 * TH_ROW_B)   // 126464
#define S2_SMEM    (S2_BIAS + 256)      // 126720

__global__ __launch_bounds__(256, 1) void stage2_mma(
    const float* __restrict__ X,
    const float* __restrict__ theta,
    const float* __restrict__ bias,
    float* __restrict__ out)
{
    extern __shared__ char smem[];
    const uint32_t sb = smem_u32(smem);

    const int tid  = threadIdx.x;
    const int lane = tid & 31;
    const int wid  = tid >> 5;
    const int gid  = lane >> 2;
    const int tig  = lane & 3;

    const int n0 = blockIdx.x * 512;    // n-half
    const int t  = blockIdx.y;
    const int bb = blockIdx.z;

    // --- async load 3 xc slabs: rows = i (32), cols = n0..n0+511 ---
    #pragma unroll
    for (int c = 0; c < KS; c++) {
        const __half* src = g_xc + (size_t)c * R_ * N_;
        #pragma unroll
        for (int j = 0; j < 8; j++) {
            int idx = j * 256 + tid;          // 0..2047
            int row = idx >> 6, c16 = idx & 63;
            cp16(sb + c * XC_SLAB_B + row * XC_ROW_B + c16 * 16,
                 src + ((size_t)(bb * CIN + row) * T_ + t) * N_ + n0 + c16 * 8);
        }
        CP_COMMIT();
    }

    // --- theta hi/lo into smem [o][ik], ik = k*32+i ---
    __half* thH = (__half*)(smem + S2_TH_HI);
    __half* thL = (__half*)(smem + S2_TH_LO);
    for (int idx = tid; idx < 64 * 96; idx += 256) {
        int o = idx / 96, ik = idx % 96;
        int k = ik >> 5, i = ik & 31;
        float v = theta[i * (COUT * KS) + o * KS + k];
        __half h = __float2half_rn(v);
        thH[o * (TH_ROW_B / 2) + ik] = h;
        thL[o * (TH_ROW_B / 2) + ik] = __float2half_rn(v - __half2float(h));
    }
    float* bias_s = (float*)(smem + S2_BIAS);
    if (tid < 64) bias_s[tid] = bias[tid];

    // per-lane ldmatrix offsets
    // A (theta, row-major [o][ik]): x4 non-trans
    const uint32_t aOff = (uint32_t)(lane & 15) * TH_ROW_B + (uint32_t)(lane >> 4) * 16;
    // B (xc, row-major [ik][n]): x4 trans — lanes 0-7: k0-7; 8-15: k8-15;
    // 16-23: k0-7 @ n+8; 24-31: k8-15 @ n+8
    const uint32_t bOff = (uint32_t)(lane & 7) * XC_ROW_B
                        + (uint32_t)((lane >> 3) & 1) * (8 * XC_ROW_B)
                        + (uint32_t)(lane >> 4) * 16;
    const uint32_t bWarp = (uint32_t)(wid * 64) * 2;   // warp n-chunk byte offset

    float acc[4][8][4];
    #pragma unroll
    for (int mt = 0; mt < 4; mt++)
        #pragma unroll
        for (int nt = 0; nt < 8; nt++)
            #pragma unroll
            for (int q = 0; q < 4; q++) acc[mt][nt][q] = 0.0f;

    #pragma unroll
    for (int c = 0; c < KS; c++) {
        if (c == 0)      CP_WAIT(2);
        else if (c == 1) CP_WAIT(1);
        else             CP_WAIT(0);
        __syncthreads();

        const uint32_t xcb = sb + c * XC_SLAB_B + bWarp + bOff;

        #pragma unroll
        for (int kst = 0; kst < 2; kst++) {
            const uint32_t ikByte = (uint32_t)(c * 32 + kst * 16) * 2;
            uint32_t ah[4][4], al[4][4];
            #pragma unroll
            for (int mt = 0; mt < 4; mt++) {
                ldmx4(ah[mt], sb + S2_TH_HI + aOff + (uint32_t)mt * (16 * TH_ROW_B) + ikByte);
                ldmx4(al[mt], sb + S2_TH_LO + aOff + (uint32_t)mt * (16 * TH_ROW_B) + ikByte);
            }
            #pragma unroll
            for (int np = 0; np < 4; np++) {
                uint32_t bx[4];
                ldmx4t(bx, xcb + (uint32_t)kst * (16 * XC_ROW_B) + np * 32);
                #pragma unroll
                for (int mt = 0; mt < 4; mt++) {
                    MMA_F16(acc[mt][2 * np],     ah[mt], bx[0], bx[1]);
                    MMA_F16(acc[mt][2 * np + 1], ah[mt], bx[2], bx[3]);
                }
                #pragma unroll
                for (int mt = 0; mt < 4; mt++) {
                    MMA_F16(acc[mt][2 * np],     al[mt], bx[0], bx[1]);
                    MMA_F16(acc[mt][2 * np + 1], al[mt], bx[2], bx[3]);
                }
            }
        }
    }

    // epilogue: bias + residual (o<32) + relu, fp32 store
    #pragma unroll
    for (int mt = 0; mt < 4; mt++) {
        #pragma unroll
        for (int half = 0; half < 2; half++) {
            const int o = mt * 16 + half * 8 + gid;
            const float bo = bias_s[o];
            const float* xr = (o < CIN)
                ? X + ((size_t)(bb * CIN + o) * T_ + t) * N_ + n0 : nullptr;
            float* orow = out + ((size_t)(bb * COUT + o) * T_ + t) * N_ + n0;
            #pragma unroll
            for (int nt = 0; nt < 8; nt++) {
                const int nn = wid * 64 + nt * 8 + tig * 2;
                float v0 = acc[mt][nt][half * 2 + 0] + bo;
                float v1 = acc[mt][nt][half * 2 + 1] + bo;
                if (xr) {
                    float2 r = *(const float2*)(xr + nn);
                    v0 += r.x; v1 += r.y;
                }
                *(float2*)(orow + nn) = make_float2(fmaxf(v0, 0.f), fmaxf(v1, 0.f));
            }
        }
    }
}

extern "C" void kernel_launch(void* const* d_in, const int* in_sizes, int n_in,
                              void* d_out, int out_size)
{
    const float* x     = (const float*)d_in[0];
    const float* Lk    = (const float*)d_in[1];
    const float* theta = (const float*)d_in[2];
    const float* bias  = (const float*)d_in[3];
    float* out = (float*)d_out;

    static bool attr_done = false;
    if (!attr_done) {
        cudaFuncSetAttribute(stage1_mma,
                             cudaFuncAttributeMaxDynamicSharedMemorySize, S1_SMEM);
        cudaFuncSetAttribute(stage2_mma,
                             cudaFuncAttributeMaxDynamicSharedMemorySize, S2_SMEM);
        attr_done = true;
    }

    split_x<<<(R_ * N_) / (256 * 4), 256>>>(x);
    split_l<<<(KS * N_ * N_) / (256 * 4), 256>>>(Lk);

    dim3 g1(N_ / 128, R_ / 256, KS);   // (8, 48, 3)
    stage1_mma<<<g1, 256, S1_SMEM>>>();

    dim3 g2(2, T_, B_);                // (2, 12, 32) = 768 CTAs
    stage2_mma<<<g2, 256, S2_SMEM>>>(x, theta, bias, out);
}

// round 8
// speedup vs baseline: 4.8913x; 1.2022x over previous
#include <cuda_runtime.h>
#include <cuda_fp16.h>
#include <cstdint>

// Problem dims (fixed by the dataset)
#define B_   32
#define CIN  32
#define T_   12
#define N_   1024
#define KS   3
#define COUT 64
#define R_   (B_ * CIN * T_)   // 12288

// Scratch (__device__ globals; no allocations allowed)
__device__ __half g_xc [(size_t)KS * R_ * N_];     // 75.5 MB fp16
__device__ __half g_xhi[(size_t)R_ * N_];          // fp16(x)
__device__ __half g_lhi[(size_t)KS * N_ * N_];     // fp16(Lk)
__device__ __half g_thH[64 * 104];                 // theta hi, rows padded to 104
__device__ __half g_thL[64 * 104];                 // theta lo

__device__ __forceinline__ uint32_t smem_u32(const void* p) {
    uint32_t a;
    asm("{ .reg .u64 t; cvta.to.shared.u64 t, %1; cvt.u32.u64 %0, t; }"
        : "=r"(a) : "l"(p));
    return a;
}
__device__ __forceinline__ void cp16(uint32_t dst, const void* src) {
    asm volatile("cp.async.cg.shared.global [%0], [%1], 16;" :: "r"(dst), "l"(src));
}
#define CP_COMMIT() asm volatile("cp.async.commit_group;" ::: "memory")
#define CP_WAIT(n)  asm volatile("cp.async.wait_group %0;" :: "n"(n) : "memory")

__device__ __forceinline__ void ldmx4(uint32_t* r, uint32_t addr) {
    asm volatile("ldmatrix.sync.aligned.m8n8.x4.shared.b16 {%0,%1,%2,%3}, [%4];"
                 : "=r"(r[0]), "=r"(r[1]), "=r"(r[2]), "=r"(r[3]) : "r"(addr));
}
__device__ __forceinline__ void ldmx4t(uint32_t* r, uint32_t addr) {
    asm volatile("ldmatrix.sync.aligned.m8n8.x4.trans.shared.b16 {%0,%1,%2,%3}, [%4];"
                 : "=r"(r[0]), "=r"(r[1]), "=r"(r[2]), "=r"(r[3]) : "r"(addr));
}

// D += A*B, m16n8k16, fp16 in / fp32 acc
#define MMA_F16(d, a, b0, b1)                                                 \
    asm volatile("mma.sync.aligned.m16n8k16.row.col.f32.f16.f16.f32 "         \
                 "{%0,%1,%2,%3}, {%4,%5,%6,%7}, {%8,%9}, {%0,%1,%2,%3};"      \
                 : "+f"((d)[0]), "+f"((d)[1]), "+f"((d)[2]), "+f"((d)[3])     \
                 : "r"((a)[0]), "r"((a)[1]), "r"((a)[2]), "r"((a)[3]),        \
                   "r"(b0), "r"(b1))

// ---------------------------------------------------------------------------
// prep kernels
// ---------------------------------------------------------------------------
__global__ __launch_bounds__(256) void split_x(const float* __restrict__ src) {
    size_t i = ((size_t)blockIdx.x * 256 + threadIdx.x) * 4;
    float4 v = *(const float4*)(src + i);
    *(__half2*)(g_xhi + i)     = __floats2half2_rn(v.x, v.y);
    *(__half2*)(g_xhi + i + 2) = __floats2half2_rn(v.z, v.w);
}
__global__ __launch_bounds__(256) void split_l(const float* __restrict__ src) {
    size_t i = ((size_t)blockIdx.x * 256 + threadIdx.x) * 4;
    float4 v = *(const float4*)(src + i);
    *(__half2*)(g_lhi + i)     = __floats2half2_rn(v.x, v.y);
    *(__half2*)(g_lhi + i + 2) = __floats2half2_rn(v.z, v.w);
}
__global__ __launch_bounds__(256) void prep_theta(const float* __restrict__ theta) {
    int idx = blockIdx.x * 256 + threadIdx.x;    // < 64*104
    int o = idx / 104, c = idx % 104;
    float v = 0.0f;
    if (c < 96) {
        int k = c >> 5, i = c & 31;
        v = theta[i * (COUT * KS) + o * KS + k];
    }
    __half h = __float2half_rn(v);
    g_thH[idx] = h;
    g_thL[idx] = __float2half_rn(v - __half2float(h));
}

// ---------------------------------------------------------------------------
// Stage 1: single-pass fp16 HMMA, 256x128 tile, KC=64, 3-stage pipeline.
// Smem rows padded to 144B (64 halfs + 16B) -> conflict-free ldmatrix.
// ---------------------------------------------------------------------------
#define KC         64
#define ROW1       144
#define STG_A      0                        // 256*144 = 36864
#define STG_B      36864                    // 128*144 = 18432
#define STG_STRIDE 55296
#define NSTAGE     3
#define S1_SMEM    (NSTAGE * STG_STRIDE)    // 165888 B

__global__ __launch_bounds__(256, 1) void stage1_mma() {
    extern __shared__ char smem[];
    const uint32_t sb = smem_u32(smem);

    const int tid  = threadIdx.x;
    const int lane = tid & 31;
    const int wid  = tid >> 5;
    const int wr   = wid >> 1;    // warp row 0..3 (64 rows each)
    const int wc   = wid & 1;     // warp col 0..1 (64 cols each)
    const int gid  = lane >> 2;
    const int tig  = lane & 3;

    const int kz    = blockIdx.z;
    const int rBase = blockIdx.y * 256;
    const int nBase = blockIdx.x * 128;

    const __half* Ax = g_xhi + (size_t)rBase * N_;
    const __half* Bh = g_lhi + ((size_t)kz * N_ + nBase) * N_;

    const uint32_t aRowOff = (uint32_t)(lane & 15) * ROW1 + (uint32_t)(lane >> 4) * 16;
    const uint32_t bRowOff = (uint32_t)((lane & 7) + ((lane >> 4) << 3)) * ROW1
                           + (uint32_t)((lane >> 3) & 1) * 16;
    const uint32_t aWarp = (uint32_t)(wr * 64) * ROW1;
    const uint32_t bWarp = (uint32_t)(wc * 64) * ROW1;

    auto issue = [&](int c) {
        const uint32_t stg = sb + (uint32_t)(c % NSTAGE) * STG_STRIDE;
        const int kofs = c * KC;
        #pragma unroll
        for (int j = 0; j < 12; j++) {
            const int idx = j * 256 + tid;
            if (j < 8) {                       // A: 256 rows x 8 cp16
                int row = idx >> 3, c16 = idx & 7;
                cp16(stg + STG_A + row * ROW1 + c16 * 16,
                     Ax + (size_t)row * N_ + kofs + c16 * 8);
            } else {                           // B: 128 rows x 8 cp16
                int q = idx - 2048, row = q >> 3, c16 = q & 7;
                cp16(stg + STG_B + row * ROW1 + c16 * 16,
                     Bh + (size_t)row * N_ + kofs + c16 * 8);
            }
        }
        CP_COMMIT();
    };

    float acc[4][8][4];
    #pragma unroll
    for (int mt = 0; mt < 4; mt++)
        #pragma unroll
        for (int nt = 0; nt < 8; nt++)
            #pragma unroll
            for (int q = 0; q < 4; q++) acc[mt][nt][q] = 0.0f;

    issue(0); issue(1);

    const int NCHUNK = N_ / KC;   // 16
    for (int c = 0; c < NCHUNK; c++) {
        if (c < NCHUNK - 1) CP_WAIT(1); else CP_WAIT(0);
        __syncthreads();
        if (c + 2 < NCHUNK) issue(c + 2);

        const uint32_t stg = sb + (uint32_t)(c % NSTAGE) * STG_STRIDE;
        const uint32_t sA  = stg + STG_A + aWarp + aRowOff;
        const uint32_t sB  = stg + STG_B + bWarp + bRowOff;

        #pragma unroll
        for (int kst = 0; kst < 4; kst++) {
            const uint32_t kb = kst * 32;
            uint32_t ax[4][4];
            #pragma unroll
            for (int mt = 0; mt < 4; mt++)
                ldmx4(ax[mt], sA + (uint32_t)mt * (16 * ROW1) + kb);
            #pragma unroll
            for (int np = 0; np < 4; np++) {
                uint32_t bh[4];
                ldmx4(bh, sB + (uint32_t)np * (16 * ROW1) + kb);
                #pragma unroll
                for (int mt = 0; mt < 4; mt++) {
                    MMA_F16(acc[mt][2 * np],     ax[mt], bh[0], bh[1]);
                    MMA_F16(acc[mt][2 * np + 1], ax[mt], bh[2], bh[3]);
                }
            }
        }
    }

    __half* C = g_xc + (size_t)kz * R_ * N_;
    const int rw = rBase + wr * 64;
    const int cw = nBase + wc * 64;
    #pragma unroll
    for (int mt = 0; mt < 4; mt++) {
        #pragma unroll
        for (int nt = 0; nt < 8; nt++) {
            const int r0 = rw + mt * 16 + gid;
            const int c0 = cw + nt * 8 + tig * 2;
            __half2 v01 = __floats2half2_rn(acc[mt][nt][0], acc[mt][nt][1]);
            __half2 v23 = __floats2half2_rn(acc[mt][nt][2], acc[mt][nt][3]);
            *(__half2*)&C[(size_t)r0 * N_ + c0]       = v01;
            *(__half2*)&C[(size_t)(r0 + 8) * N_ + c0] = v23;
        }
    }
}

// ---------------------------------------------------------------------------
// Stage 2 (HMMA, occupancy-optimized): per (b,t,n-block 128):
// D[o=64][n=128] = sum_ik th[ik][o] * xc[ik][n];  theta hi+lo 2-pass.
// 8 warps: 4 o-rows x 2 n-cols, warp tile 16x64, acc = 32 regs.
// ---------------------------------------------------------------------------
#define XC_ROW   272                        // 128 halfs + 16B pad
#define XC_SLAB  (32 * XC_ROW)              // 8704
#define TH_ROW   208                        // 104 halfs
#define S2_TH_HI (3 * XC_SLAB)              // 26112
#define S2_TH_LO (S2_TH_HI + 64 * TH_ROW)   // 39424
#define S2_SMEM  (S2_TH_LO + 64 * TH_ROW)   // 52736

__global__ __launch_bounds__(256) void stage2_mma(
    const float* __restrict__ X,
    const float* __restrict__ bias,
    float* __restrict__ out)
{
    extern __shared__ char smem[];
    const uint32_t sb = smem_u32(smem);

    const int tid  = threadIdx.x;
    const int lane = tid & 31;
    const int wid  = tid >> 5;
    const int wr2  = wid >> 1;   // o-row 0..3 (16 each)
    const int wc2  = wid & 1;    // n-col 0..1 (64 each)
    const int gid  = lane >> 2;
    const int tig  = lane & 3;

    const int n0 = blockIdx.x * 128;
    const int t  = blockIdx.y;
    const int bb = blockIdx.z;

    // group 0: theta hi+lo (1664 cp16)
    for (int idx = tid; idx < 1664; idx += 256) {
        int m = idx >= 832;
        int q = idx - m * 832;
        int row = q / 13, c16 = q % 13;
        const __half* src = m ? g_thL : g_thH;
        cp16(sb + (m ? S2_TH_LO : S2_TH_HI) + row * TH_ROW + c16 * 16,
             src + row * 104 + c16 * 8);
    }
    CP_COMMIT();

    // groups 1..3: xc slabs (512 cp16 each)
    #pragma unroll
    for (int c = 0; c < KS; c++) {
        const __half* src = g_xc + (size_t)c * R_ * N_;
        #pragma unroll
        for (int j = 0; j < 2; j++) {
            int idx = j * 256 + tid;          // 0..511
            int row = idx >> 4, c16 = idx & 15;
            cp16(sb + c * XC_SLAB + row * XC_ROW + c16 * 16,
                 src + ((size_t)(bb * CIN + row) * T_ + t) * N_ + n0 + c16 * 8);
        }
        CP_COMMIT();
    }

    // ldmatrix per-lane offsets
    const uint32_t aOff = (uint32_t)(lane & 15) * TH_ROW + (uint32_t)(lane >> 4) * 16
                        + (uint32_t)wr2 * (16 * TH_ROW);
    const uint32_t bOff = (uint32_t)(lane & 15) * XC_ROW + (uint32_t)(lane >> 4) * 16
                        + (uint32_t)wc2 * 128;

    float acc[8][4];
    #pragma unroll
    for (int nt = 0; nt < 8; nt++)
        #pragma unroll
        for (int q = 0; q < 4; q++) acc[nt][q] = 0.0f;

    #pragma unroll
    for (int c = 0; c < KS; c++) {
        if (c == 0)      CP_WAIT(2);
        else if (c == 1) CP_WAIT(1);
        else             CP_WAIT(0);
        __syncthreads();

        #pragma unroll
        for (int kst = 0; kst < 2; kst++) {
            const uint32_t ikByte = (uint32_t)(c * 32 + kst * 16) * 2;
            uint32_t ah[4], al[4];
            ldmx4(ah, sb + S2_TH_HI + aOff + ikByte);
            ldmx4(al, sb + S2_TH_LO + aOff + ikByte);
            #pragma unroll
            for (int np = 0; np < 4; np++) {
                uint32_t bx[4];
                ldmx4t(bx, sb + c * XC_SLAB + (uint32_t)kst * (16 * XC_ROW)
                           + bOff + np * 32);
                MMA_F16(acc[2 * np],     ah, bx[0], bx[1]);
                MMA_F16(acc[2 * np + 1], ah, bx[2], bx[3]);
                MMA_F16(acc[2 * np],     al, bx[0], bx[1]);
                MMA_F16(acc[2 * np + 1], al, bx[2], bx[3]);
            }
        }
    }

    // epilogue: bias + residual (o<32) + relu
    #pragma unroll
    for (int half = 0; half < 2; half++) {
        const int o = wr2 * 16 + half * 8 + gid;
        const float bo = __ldg(bias + o);
        const float* xr = (o < CIN)
            ? X + ((size_t)(bb * CIN + o) * T_ + t) * N_ + n0 : nullptr;
        float* orow = out + ((size_t)(bb * COUT + o) * T_ + t) * N_ + n0;
        #pragma unroll
        for (int nt = 0; nt < 8; nt++) {
            const int nn = wc2 * 64 + nt * 8 + tig * 2;
            float v0 = acc[nt][half * 2 + 0] + bo;
            float v1 = acc[nt][half * 2 + 1] + bo;
            if (xr) {
                float2 r = *(const float2*)(xr + nn);
                v0 += r.x; v1 += r.y;
            }
            *(float2*)(orow + nn) = make_float2(fmaxf(v0, 0.f), fmaxf(v1, 0.f));
        }
    }
}

extern "C" void kernel_launch(void* const* d_in, const int* in_sizes, int n_in,
                              void* d_out, int out_size)
{
    const float* x     = (const float*)d_in[0];
    const float* Lk    = (const float*)d_in[1];
    const float* theta = (const float*)d_in[2];
    const float* bias  = (const float*)d_in[3];
    float* out = (float*)d_out;

    static bool attr_done = false;
    if (!attr_done) {
        cudaFuncSetAttribute(stage1_mma,
                             cudaFuncAttributeMaxDynamicSharedMemorySize, S1_SMEM);
        cudaFuncSetAttribute(stage2_mma,
                             cudaFuncAttributeMaxDynamicSharedMemorySize, S2_SMEM);
        attr_done = true;
    }

    split_x<<<(R_ * N_) / (256 * 4), 256>>>(x);
    split_l<<<(KS * N_ * N_) / (256 * 4), 256>>>(Lk);
    prep_theta<<<(64 * 104) / 256, 256>>>(theta);

    dim3 g1(N_ / 128, R_ / 256, KS);   // (8, 48, 3)
    stage1_mma<<<g1, 256, S1_SMEM>>>();

    dim3 g2(N_ / 128, T_, B_);         // (8, 12, 32) = 3072 CTAs
    stage2_mma<<<g2, 256, S2_SMEM>>>(x, bias, out);
}

// round 9
// speedup vs baseline: 5.3531x; 1.0944x over previous
#include <cuda_runtime.h>
#include <cuda_fp16.h>
#include <cstdint>

// Problem dims (fixed by the dataset)
#define B_   32
#define CIN  32
#define T_   12
#define N_   1024
#define KS   3
#define COUT 64
#define R_   (B_ * CIN * T_)   // 12288

// Scratch (__device__ globals; no allocations allowed)
__device__ __half g_xc [(size_t)KS * R_ * N_];     // 75.5 MB fp16
__device__ __half g_xhi[(size_t)R_ * N_];          // fp16(x)
__device__ __half g_lhi[(size_t)KS * N_ * N_];     // fp16(Lk)
__device__ __half g_thH[64 * 104];                 // theta hi, rows padded to 104
__device__ __half g_thL[64 * 104];                 // theta lo

__device__ __forceinline__ uint32_t smem_u32(const void* p) {
    uint32_t a;
    asm("{ .reg .u64 t; cvta.to.shared.u64 t, %1; cvt.u32.u64 %0, t; }"
        : "=r"(a) : "l"(p));
    return a;
}
__device__ __forceinline__ void cp16(uint32_t dst, const void* src) {
    asm volatile("cp.async.cg.shared.global [%0], [%1], 16;" :: "r"(dst), "l"(src));
}
#define CP_COMMIT() asm volatile("cp.async.commit_group;" ::: "memory")
#define CP_WAIT(n)  asm volatile("cp.async.wait_group %0;" :: "n"(n) : "memory")

__device__ __forceinline__ void ldmx4(uint32_t* r, uint32_t addr) {
    asm volatile("ldmatrix.sync.aligned.m8n8.x4.shared.b16 {%0,%1,%2,%3}, [%4];"
                 : "=r"(r[0]), "=r"(r[1]), "=r"(r[2]), "=r"(r[3]) : "r"(addr));
}
__device__ __forceinline__ void ldmx4t(uint32_t* r, uint32_t addr) {
    asm volatile("ldmatrix.sync.aligned.m8n8.x4.trans.shared.b16 {%0,%1,%2,%3}, [%4];"
                 : "=r"(r[0]), "=r"(r[1]), "=r"(r[2]), "=r"(r[3]) : "r"(addr));
}

// D += A*B, m16n8k16, fp16 in / fp32 acc
#define MMA_F16(d, a, b0, b1)                                                 \
    asm volatile("mma.sync.aligned.m16n8k16.row.col.f32.f16.f16.f32 "         \
                 "{%0,%1,%2,%3}, {%4,%5,%6,%7}, {%8,%9}, {%0,%1,%2,%3};"      \
                 : "+f"((d)[0]), "+f"((d)[1]), "+f"((d)[2]), "+f"((d)[3])     \
                 : "r"((a)[0]), "r"((a)[1]), "r"((a)[2]), "r"((a)[3]),        \
                   "r"(b0), "r"(b1))

// ---------------------------------------------------------------------------
// prep kernels
// ---------------------------------------------------------------------------
__global__ __launch_bounds__(256) void split_x(const float* __restrict__ src) {
    size_t i = ((size_t)blockIdx.x * 256 + threadIdx.x) * 4;
    float4 v = *(const float4*)(src + i);
    *(__half2*)(g_xhi + i)     = __floats2half2_rn(v.x, v.y);
    *(__half2*)(g_xhi + i + 2) = __floats2half2_rn(v.z, v.w);
}
__global__ __launch_bounds__(256) void split_l(const float* __restrict__ src) {
    size_t i = ((size_t)blockIdx.x * 256 + threadIdx.x) * 4;
    float4 v = *(const float4*)(src + i);
    *(__half2*)(g_lhi + i)     = __floats2half2_rn(v.x, v.y);
    *(__half2*)(g_lhi + i + 2) = __floats2half2_rn(v.z, v.w);
}
__global__ __launch_bounds__(256) void prep_theta(const float* __restrict__ theta) {
    int idx = blockIdx.x * 256 + threadIdx.x;    // < 64*104
    int o = idx / 104, c = idx % 104;
    float v = 0.0f;
    if (c < 96) {
        int k = c >> 5, i = c & 31;
        v = theta[i * (COUT * KS) + o * KS + k];
    }
    __half h = __float2half_rn(v);
    g_thH[idx] = h;
    g_thL[idx] = __float2half_rn(v - __half2float(h));
}

// ---------------------------------------------------------------------------
// Stage 1: single-pass fp16 HMMA, 128x128 tile, KC=64, 3-stage, 2 CTAs/SM.
// 8 warps = 4 warp-rows(32) x 2 warp-cols(64); acc = 64 regs.
// Smem rows padded to 144B -> conflict-free ldmatrix.
// ---------------------------------------------------------------------------
#define KC         64
#define ROW1       144
#define STG_A      0                        // 128*144 = 18432
#define STG_B      18432                    // 128*144 = 18432
#define STG_STRIDE 36864
#define NSTAGE     3
#define S1_SMEM    (NSTAGE * STG_STRIDE)    // 110592 B

__global__ __launch_bounds__(256, 2) void stage1_mma() {
    extern __shared__ char smem[];
    const uint32_t sb = smem_u32(smem);

    const int tid  = threadIdx.x;
    const int lane = tid & 31;
    const int wid  = tid >> 5;
    const int wr   = wid >> 1;    // warp row 0..3 (32 rows each)
    const int wc   = wid & 1;     // warp col 0..1 (64 cols each)
    const int gid  = lane >> 2;
    const int tig  = lane & 3;

    const int kz    = blockIdx.z;
    const int rBase = blockIdx.y * 128;
    const int nBase = blockIdx.x * 128;

    const __half* Ax = g_xhi + (size_t)rBase * N_;
    const __half* Bh = g_lhi + ((size_t)kz * N_ + nBase) * N_;

    const uint32_t aRowOff = (uint32_t)(lane & 15) * ROW1 + (uint32_t)(lane >> 4) * 16;
    const uint32_t bRowOff = (uint32_t)((lane & 7) + ((lane >> 4) << 3)) * ROW1
                           + (uint32_t)((lane >> 3) & 1) * 16;
    const uint32_t aWarp = (uint32_t)(wr * 32) * ROW1;
    const uint32_t bWarp = (uint32_t)(wc * 64) * ROW1;

    auto issue = [&](int c) {
        const uint32_t stg = sb + (uint32_t)(c % NSTAGE) * STG_STRIDE;
        const int kofs = c * KC;
        #pragma unroll
        for (int j = 0; j < 8; j++) {
            const int idx = j * 256 + tid;       // 0..2047
            if (j < 4) {                          // A: 128 rows x 8 cp16
                int row = idx >> 3, c16 = idx & 7;
                cp16(stg + STG_A + row * ROW1 + c16 * 16,
                     Ax + (size_t)row * N_ + kofs + c16 * 8);
            } else {                              // B: 128 rows x 8 cp16
                int q = idx - 1024, row = q >> 3, c16 = q & 7;
                cp16(stg + STG_B + row * ROW1 + c16 * 16,
                     Bh + (size_t)row * N_ + kofs + c16 * 8);
            }
        }
        CP_COMMIT();
    };

    float acc[2][8][4];
    #pragma unroll
    for (int mt = 0; mt < 2; mt++)
        #pragma unroll
        for (int nt = 0; nt < 8; nt++)
            #pragma unroll
            for (int q = 0; q < 4; q++) acc[mt][nt][q] = 0.0f;

    issue(0); issue(1);

    const int NCHUNK = N_ / KC;   // 16
    for (int c = 0; c < NCHUNK; c++) {
        if (c < NCHUNK - 1) CP_WAIT(1); else CP_WAIT(0);
        __syncthreads();
        if (c + 2 < NCHUNK) issue(c + 2);

        const uint32_t stg = sb + (uint32_t)(c % NSTAGE) * STG_STRIDE;
        const uint32_t sA  = stg + STG_A + aWarp + aRowOff;
        const uint32_t sB  = stg + STG_B + bWarp + bRowOff;

        #pragma unroll
        for (int kst = 0; kst < 4; kst++) {
            const uint32_t kb = kst * 32;
            uint32_t ax[2][4];
            #pragma unroll
            for (int mt = 0; mt < 2; mt++)
                ldmx4(ax[mt], sA + (uint32_t)mt * (16 * ROW1) + kb);
            #pragma unroll
            for (int np = 0; np < 4; np++) {
                uint32_t bh[4];
                ldmx4(bh, sB + (uint32_t)np * (16 * ROW1) + kb);
                #pragma unroll
                for (int mt = 0; mt < 2; mt++) {
                    MMA_F16(acc[mt][2 * np],     ax[mt], bh[0], bh[1]);
                    MMA_F16(acc[mt][2 * np + 1], ax[mt], bh[2], bh[3]);
                }
            }
        }
    }

    __half* C = g_xc + (size_t)kz * R_ * N_;
    const int rw = rBase + wr * 32;
    const int cw = nBase + wc * 64;
    #pragma unroll
    for (int mt = 0; mt < 2; mt++) {
        #pragma unroll
        for (int nt = 0; nt < 8; nt++) {
            const int r0 = rw + mt * 16 + gid;
            const int c0 = cw + nt * 8 + tig * 2;
            __half2 v01 = __floats2half2_rn(acc[mt][nt][0], acc[mt][nt][1]);
            __half2 v23 = __floats2half2_rn(acc[mt][nt][2], acc[mt][nt][3]);
            *(__half2*)&C[(size_t)r0 * N_ + c0]       = v01;
            *(__half2*)&C[(size_t)(r0 + 8) * N_ + c0] = v23;
        }
    }
}

// ---------------------------------------------------------------------------
// Stage 2 (HMMA, occupancy-optimized): per (b,t,n-block 128):
// D[o=64][n=128] = sum_ik th[ik][o] * xc[ik][n];  theta hi+lo 2-pass.
// ---------------------------------------------------------------------------
#define XC_ROW   272                        // 128 halfs + 16B pad
#define XC_SLAB  (32 * XC_ROW)              // 8704
#define TH_ROW   208                        // 104 halfs
#define S2_TH_HI (3 * XC_SLAB)              // 26112
#define S2_TH_LO (S2_TH_HI + 64 * TH_ROW)   // 39424
#define S2_SMEM  (S2_TH_LO + 64 * TH_ROW)   // 52736

__global__ __launch_bounds__(256) void stage2_mma(
    const float* __restrict__ X,
    const float* __restrict__ bias,
    float* __restrict__ out)
{
    extern __shared__ char smem[];
    const uint32_t sb = smem_u32(smem);

    const int tid  = threadIdx.x;
    const int lane = tid & 31;
    const int wid  = tid >> 5;
    const int wr2  = wid >> 1;   // o-row 0..3 (16 each)
    const int wc2  = wid & 1;    // n-col 0..1 (64 each)
    const int gid  = lane >> 2;
    const int tig  = lane & 3;

    const int n0 = blockIdx.x * 128;
    const int t  = blockIdx.y;
    const int bb = blockIdx.z;

    // group 0: theta hi+lo (1664 cp16)
    for (int idx = tid; idx < 1664; idx += 256) {
        int m = idx >= 832;
        int q = idx - m * 832;
        int row = q / 13, c16 = q % 13;
        const __half* src = m ? g_thL : g_thH;
        cp16(sb + (m ? S2_TH_LO : S2_TH_HI) + row * TH_ROW + c16 * 16,
             src + row * 104 + c16 * 8);
    }
    CP_COMMIT();

    // groups 1..3: xc slabs (512 cp16 each)
    #pragma unroll
    for (int c = 0; c < KS; c++) {
        const __half* src = g_xc + (size_t)c * R_ * N_;
        #pragma unroll
        for (int j = 0; j < 2; j++) {
            int idx = j * 256 + tid;
            int row = idx >> 4, c16 = idx & 15;
            cp16(sb + c * XC_SLAB + row * XC_ROW + c16 * 16,
                 src + ((size_t)(bb * CIN + row) * T_ + t) * N_ + n0 + c16 * 8);
        }
        CP_COMMIT();
    }

    const uint32_t aOff = (uint32_t)(lane & 15) * TH_ROW + (uint32_t)(lane >> 4) * 16
                        + (uint32_t)wr2 * (16 * TH_ROW);
    const uint32_t bOff = (uint32_t)(lane & 15) * XC_ROW + (uint32_t)(lane >> 4) * 16
                        + (uint32_t)wc2 * 128;

    float acc[8][4];
    #pragma unroll
    for (int nt = 0; nt < 8; nt++)
        #pragma unroll
        for (int q = 0; q < 4; q++) acc[nt][q] = 0.0f;

    #pragma unroll
    for (int c = 0; c < KS; c++) {
        if (c == 0)      CP_WAIT(2);
        else if (c == 1) CP_WAIT(1);
        else             CP_WAIT(0);
        __syncthreads();

        #pragma unroll
        for (int kst = 0; kst < 2; kst++) {
            const uint32_t ikByte = (uint32_t)(c * 32 + kst * 16) * 2;
            uint32_t ah[4], al[4];
            ldmx4(ah, sb + S2_TH_HI + aOff + ikByte);
            ldmx4(al, sb + S2_TH_LO + aOff + ikByte);
            #pragma unroll
            for (int np = 0; np < 4; np++) {
                uint32_t bx[4];
                ldmx4t(bx, sb + c * XC_SLAB + (uint32_t)kst * (16 * XC_ROW)
                           + bOff + np * 32);
                MMA_F16(acc[2 * np],     ah, bx[0], bx[1]);
                MMA_F16(acc[2 * np + 1], ah, bx[2], bx[3]);
                MMA_F16(acc[2 * np],     al, bx[0], bx[1]);
                MMA_F16(acc[2 * np + 1], al, bx[2], bx[3]);
            }
        }
    }

    // epilogue: bias + residual (o<32) + relu
    #pragma unroll
    for (int half = 0; half < 2; half++) {
        const int o = wr2 * 16 + half * 8 + gid;
        const float bo = __ldg(bias + o);
        const float* xr = (o < CIN)
            ? X + ((size_t)(bb * CIN + o) * T_ + t) * N_ + n0 : nullptr;
        float* orow = out + ((size_t)(bb * COUT + o) * T_ + t) * N_ + n0;
        #pragma unroll
        for (int nt = 0; nt < 8; nt++) {
            const int nn = wc2 * 64 + nt * 8 + tig * 2;
            float v0 = acc[nt][half * 2 + 0] + bo;
            float v1 = acc[nt][half * 2 + 1] + bo;
            if (xr) {
                float2 r = *(const float2*)(xr + nn);
                v0 += r.x; v1 += r.y;
            }
            *(float2*)(orow + nn) = make_float2(fmaxf(v0, 0.f), fmaxf(v1, 0.f));
        }
    }
}

extern "C" void kernel_launch(void* const* d_in, const int* in_sizes, int n_in,
                              void* d_out, int out_size)
{
    const float* x     = (const float*)d_in[0];
    const float* Lk    = (const float*)d_in[1];
    const float* theta = (const float*)d_in[2];
    const float* bias  = (const float*)d_in[3];
    float* out = (float*)d_out;

    static bool attr_done = false;
    if (!attr_done) {
        cudaFuncSetAttribute(stage1_mma,
                             cudaFuncAttributeMaxDynamicSharedMemorySize, S1_SMEM);
        cudaFuncSetAttribute(stage2_mma,
                             cudaFuncAttributeMaxDynamicSharedMemorySize, S2_SMEM);
        attr_done = true;
    }

    split_x<<<(R_ * N_) / (256 * 4), 256>>>(x);
    split_l<<<(KS * N_ * N_) / (256 * 4), 256>>>(Lk);
    prep_theta<<<(64 * 104) / 256, 256>>>(theta);

    dim3 g1(N_ / 128, R_ / 128, KS);   // (8, 96, 3) = 2304 CTAs
    stage1_mma<<<g1, 256, S1_SMEM>>>();

    dim3 g2(N_ / 128, T_, B_);         // (8, 12, 32) = 3072 CTAs
    stage2_mma<<<g2, 256, S2_SMEM>>>(x, bias, out);
}